// round 14
// baseline (speedup 1.0000x reference)
#include <cuda_runtime.h>
#include <cuda_bf16.h>
#include <math.h>
#include <stdint.h>

// Problem constants (fixed by the reference)
#define Nn 100000
#define Ee 400000
#define Rr 4
#define Gg 64
#define INF 64
#define Hh 128
#define Cc 2
#define RN (Rr * Nn)        // 400000
#define RE (Rr * Ee)        // 1600000

#define KU_L 256            // stacked K for layer GEMMs (512 k / 2)
#define KU_I 32             // input GEMM (64 k / 2)
#define WST  (2 * Hh * KU_L)
#define WST_IN (2 * Hh * KU_I)

// ---------------- scratch (device globals; no allocation allowed) ----------
__device__ float    g_h   [(size_t)Nn * Hh];
__device__ float    g_out2[(size_t)Nn * Hh];
__device__ int      g_cout[RN];
__device__ int      g_cin [RN];
__device__ int      g_rp  [RN + 1];
__device__ int      g_bs  [512];
__device__ int      g_eidx  [RE];
__device__ float    g_escale[RE];
__device__ uint32_t g_wst   [2 * WST];
__device__ uint32_t g_wtin  [WST_IN];
__device__ float    g_bsum  [2 * Hh];
__device__ uint32_t g_Ah[(size_t)Nn * KU_L];
__device__ uint32_t g_Al[(size_t)Nn * KU_L];
__device__ float    g_pool[Gg * Hh];
__device__ float    g_cnt [Gg];

// ---------------- helpers ----------------------------------------------------
__device__ __forceinline__ uint32_t packbf_hi(float a, float b, float& ra, float& rb) {
    __nv_bfloat162 h = __floats2bfloat162_rn(a, b);
    ra = a - __bfloat162float(h.x);
    rb = b - __bfloat162float(h.y);
    return *reinterpret_cast<uint32_t*>(&h);
}
__device__ __forceinline__ uint32_t packbf(float a, float b) {
    __nv_bfloat162 h = __floats2bfloat162_rn(a, b);
    return *reinterpret_cast<uint32_t*>(&h);
}

// ---------------- degrees ----------------------------------------------------
__global__ void degree_kernel(const int* __restrict__ src, const int* __restrict__ dst) {
    int i = blockIdx.x * blockDim.x + threadIdx.x;
    if (i < RE) {
        int r = i / Ee;
        atomicAdd(&g_cout[r * Nn + src[i]], 1);
        atomicAdd(&g_cin [r * Nn + dst[i]], 1);
    }
}

// ---------------- CSR build: scan + fill --------------------------------------
__global__ void scan1_kernel() {
    __shared__ int ts[256];
    int b = blockIdx.x, t = threadIdx.x;
    int i0 = b * 1024 + t * 4;
    int v0 = (i0 + 0 < RN) ? g_cin[i0 + 0] : 0;
    int v1 = (i0 + 1 < RN) ? g_cin[i0 + 1] : 0;
    int v2 = (i0 + 2 < RN) ? g_cin[i0 + 2] : 0;
    int v3 = (i0 + 3 < RN) ? g_cin[i0 + 3] : 0;
    int tot = v0 + v1 + v2 + v3;
    ts[t] = tot;
    __syncthreads();
    for (int off = 1; off < 256; off <<= 1) {
        int x = (t >= off) ? ts[t - off] : 0;
        __syncthreads();
        ts[t] += x;
        __syncthreads();
    }
    int excl = ts[t] - tot;
    if (i0 + 0 < RN) g_rp[i0 + 0] = excl;
    if (i0 + 1 < RN) g_rp[i0 + 1] = excl + v0;
    if (i0 + 2 < RN) g_rp[i0 + 2] = excl + v0 + v1;
    if (i0 + 3 < RN) g_rp[i0 + 3] = excl + v0 + v1 + v2;
    if (t == 255) g_bs[b] = ts[255];
}
__global__ void scan2_kernel(int nb) {
    __shared__ int ts[512];
    int t = threadIdx.x;
    int v = (t < nb) ? g_bs[t] : 0;
    ts[t] = v;
    __syncthreads();
    for (int off = 1; off < 512; off <<= 1) {
        int x = (t >= off) ? ts[t - off] : 0;
        __syncthreads();
        ts[t] += x;
        __syncthreads();
    }
    g_bs[t] = ts[t] - v;
}
__global__ void scan3_kernel() {
    int b = blockIdx.x, t = threadIdx.x;
    int add = g_bs[b];
    int i0 = b * 1024 + t * 4;
#pragma unroll
    for (int q = 0; q < 4; ++q)
        if (i0 + q < RN) g_rp[i0 + q] += add;
    if (b == 0 && t == 0) g_rp[RN] = RE;
}
__global__ void fill_kernel(const int* __restrict__ src, const int* __restrict__ dst) {
    int i = blockIdx.x * blockDim.x + threadIdx.x;
    if (i >= RE) return;
    int r = i / Ee;
    int s = src[i];
    int idx = r * Nn + dst[i];
    int pos = g_rp[idx] + atomicAdd(&g_cin[idx], 1);
    g_eidx[pos] = s;
    g_escale[pos] = rsqrtf((float)max(g_cout[r * Nn + s], 1));
}

// ---------------- weight prep ---------------------------------------------------
__global__ void wprep_kernel(const float* __restrict__ W1,
                             const float* __restrict__ W2,
                             const float* __restrict__ Win) {
    int i = blockIdx.x * blockDim.x + threadIdx.x;
    const int TL = 2 * Hh * KU_L;
    if (i < TL) {
        int l = i >> 15;
        int rem = i & 32767;
        int n = rem >> 8, j = rem & 255;
        int r = j >> 6, ku = j & 63;
        const float* W = (l == 0 ? W1 : W2) + (size_t)r * Hh * Hh;
        float w0 = W[(2 * ku) * Hh + n];
        float w1 = W[(2 * ku + 1) * Hh + n];
        float r0, r1;
        uint32_t hi = packbf_hi(w0, w1, r0, r1);
        size_t base = (size_t)l * WST;
        g_wst[base + (size_t)n * KU_L + j] = hi;
        g_wst[base + (size_t)Hh * KU_L + (size_t)n * KU_L + j] = packbf(r0, r1);
    } else {
        int j = i - TL;
        if (j < Hh * KU_I) {
            int n = j >> 5, ku = j & 31;
            float w0 = Win[(2 * ku) * Hh + n];
            float w1 = Win[(2 * ku + 1) * Hh + n];
            float r0, r1;
            uint32_t hi = packbf_hi(w0, w1, r0, r1);
            g_wtin[n * KU_I + ku] = hi;
            g_wtin[Hh * KU_I + n * KU_I + ku] = packbf(r0, r1);
        }
    }
}

__global__ void bsum_kernel(const float* __restrict__ b1,
                            const float* __restrict__ b2) {
    int j = threadIdx.x;
    if (j < Hh) {
        float s1 = 0.f, s2 = 0.f;
        for (int r = 0; r < Rr; ++r) { s1 += b1[r * Hh + j]; s2 += b2[r * Hh + j]; }
        g_bsum[j] = s1; g_bsum[Hh + j] = s2;
    }
}

// ---------------- fp32 -> bf16 hi/lo planes for x -----------------------------
__global__ void conv_kernel(const float* __restrict__ src, int KU2,
                            uint32_t* __restrict__ ph, uint32_t* __restrict__ pl,
                            int total) {
    int i = blockIdx.x * blockDim.x + threadIdx.x;
    if (i >= total) return;
    int row = i / KU2, ku = i - row * KU2;
    float2 f = *(const float2*)(src + (size_t)row * (2 * KU2) + 2 * ku);
    float r0, r1;
    ph[i] = packbf_hi(f.x, f.y, r0, r1);
    pl[i] = packbf(r0, r1);
}

// ---------------- CSR gather: warp per (node, relation) ----------------------
__global__ void gather_kernel(const float* __restrict__ h,
                              uint32_t* __restrict__ Ah, uint32_t* __restrict__ Al) {
    int w = (blockIdx.x * blockDim.x + threadIdx.x) >> 5;
    int lane = threadIdx.x & 31;
    if (w >= Nn) return;
    int r = blockIdx.y;
    int idx = r * Nn + w;
    int p0 = __ldg(&g_rp[idx]);
    int p1 = __ldg(&g_rp[idx + 1]);
    float4 acc = make_float4(0.f, 0.f, 0.f, 0.f);
    int p = p0;
    for (; p + 4 <= p1; p += 4) {
        int s0 = __ldg(&g_eidx[p]);
        int s1 = __ldg(&g_eidx[p + 1]);
        int s2 = __ldg(&g_eidx[p + 2]);
        int s3 = __ldg(&g_eidx[p + 3]);
        float c0 = __ldg(&g_escale[p]);
        float c1 = __ldg(&g_escale[p + 1]);
        float c2 = __ldg(&g_escale[p + 2]);
        float c3 = __ldg(&g_escale[p + 3]);
        float4 v0 = *(const float4*)&h[(size_t)s0 * Hh + lane * 4];
        float4 v1 = *(const float4*)&h[(size_t)s1 * Hh + lane * 4];
        float4 v2 = *(const float4*)&h[(size_t)s2 * Hh + lane * 4];
        float4 v3 = *(const float4*)&h[(size_t)s3 * Hh + lane * 4];
        acc.x = fmaf(v0.x, c0, acc.x); acc.y = fmaf(v0.y, c0, acc.y);
        acc.z = fmaf(v0.z, c0, acc.z); acc.w = fmaf(v0.w, c0, acc.w);
        acc.x = fmaf(v1.x, c1, acc.x); acc.y = fmaf(v1.y, c1, acc.y);
        acc.z = fmaf(v1.z, c1, acc.z); acc.w = fmaf(v1.w, c1, acc.w);
        acc.x = fmaf(v2.x, c2, acc.x); acc.y = fmaf(v2.y, c2, acc.y);
        acc.z = fmaf(v2.z, c2, acc.z); acc.w = fmaf(v2.w, c2, acc.w);
        acc.x = fmaf(v3.x, c3, acc.x); acc.y = fmaf(v3.y, c3, acc.y);
        acc.z = fmaf(v3.z, c3, acc.z); acc.w = fmaf(v3.w, c3, acc.w);
    }
    for (; p < p1; ++p) {
        int s = __ldg(&g_eidx[p]);
        float sc = __ldg(&g_escale[p]);
        float4 v = *(const float4*)&h[(size_t)s * Hh + lane * 4];
        acc.x = fmaf(v.x, sc, acc.x);
        acc.y = fmaf(v.y, sc, acc.y);
        acc.z = fmaf(v.z, sc, acc.z);
        acc.w = fmaf(v.w, sc, acc.w);
    }
    float ri = rsqrtf((float)max(p1 - p0, 1));   // deg_in from CSR row extent
    acc.x *= ri; acc.y *= ri; acc.z *= ri; acc.w *= ri;
    float r0, r1, r2, r3;
    uint32_t h0 = packbf_hi(acc.x, acc.y, r0, r1);
    uint32_t h1 = packbf_hi(acc.z, acc.w, r2, r3);
    size_t base = (size_t)w * KU_L + r * 64 + 2 * lane;
    *(uint2*)&Ah[base] = make_uint2(h0, h1);
    *(uint2*)&Al[base] = make_uint2(packbf(r0, r1), packbf(r2, r3));
}

// ---------------- bf16 3-pass GEMM: 256 threads, 64x64 warp tiles ------------
// CTA tile 256(M) x 128(N); 8 warps in 4(M)x2(N); warp tile 64x64.
// 2-stage cp.async; per stage: A planes 2x(256x36) + B planes 2x(128x36) u32.
#define SMS 36
#define TA_U (256 * SMS)
#define TB_U (128 * SMS)
#define STAGE2_U (2 * TA_U + 2 * TB_U)   // 27648 u32 = 110592 B

__device__ __forceinline__ void mma16(float* c, const uint32_t* a,
                                      uint32_t b0, uint32_t b1) {
    asm volatile(
        "mma.sync.aligned.m16n8k16.row.col.f32.bf16.bf16.f32 "
        "{%0,%1,%2,%3}, {%4,%5,%6,%7}, {%8,%9}, {%0,%1,%2,%3};"
        : "+f"(c[0]), "+f"(c[1]), "+f"(c[2]), "+f"(c[3])
        : "r"(a[0]), "r"(a[1]), "r"(a[2]), "r"(a[3]), "r"(b0), "r"(b1));
}
__device__ __forceinline__ void cpa16(uint32_t daddr, const uint32_t* src, uint32_t nbytes) {
    asm volatile("cp.async.cg.shared.global [%0], [%1], 16, %2;"
                 :: "r"(daddr), "l"(src), "r"(nbytes) : "memory");
}

__global__ void __launch_bounds__(256)
bf16_gemm_kernel(const uint32_t* __restrict__ Ah, const uint32_t* __restrict__ Al,
                 int KU,
                 const uint32_t* __restrict__ Wp,
                 const float* __restrict__ cbias,   // nullable
                 int relu_out,
                 float* __restrict__ C, int n) {
    extern __shared__ uint32_t smu[];

    const int tid = threadIdx.x;
    const int lane = tid & 31, warp = tid >> 5;   // 8 warps
    const int wm = warp >> 1, wn = warp & 1;      // wm 0..3 (64 rows), wn 0..1
    const int g = lane >> 2, t = lane & 3;
    const int row0 = blockIdx.x * 256;
    const int iters = KU >> 5;

    // A staging: thread -> its own row (256 rows), 32 u32 per plane
    const int grow_s = row0 + tid;
    const int arow = (grow_s < n) ? grow_s : (n - 1);
    const uint32_t avalid = (grow_s < n) ? 16u : 0u;
    // B staging: 2 threads per row
    const int br = tid >> 1;
    const int bc = (tid & 1) * 16;

    uint32_t smbase = (uint32_t)__cvta_generic_to_shared(smu);

    float acc[4][8][4];
#pragma unroll
    for (int mf = 0; mf < 4; ++mf)
#pragma unroll
        for (int nf = 0; nf < 8; ++nf)
#pragma unroll
            for (int q = 0; q < 4; ++q) acc[mf][nf][q] = 0.f;

#define ISSUE(CI) do {                                                          \
    const int uc_ = (CI) * 32;                                                  \
    const uint32_t dbase_ = smbase + ((CI) & 1) * (STAGE2_U * 4);               \
    const uint32_t doffA_ = (uint32_t)(tid * SMS) * 4;                          \
    const uint32_t* pAh_ = Ah + (size_t)arow * KU + uc_;                        \
    const uint32_t* pAl_ = Al + (size_t)arow * KU + uc_;                        \
    _Pragma("unroll")                                                           \
    for (int q = 0; q < 8; ++q) {                                               \
        cpa16(dbase_ + doffA_ + q * 16,              pAh_ + q * 4, avalid);     \
        cpa16(dbase_ + TA_U * 4 + doffA_ + q * 16,   pAl_ + q * 4, avalid);     \
    }                                                                           \
    const uint32_t doffB_ = (uint32_t)(br * SMS + bc) * 4;                      \
    const uint32_t* pWh_ = Wp + (size_t)br * KU + uc_ + bc;                     \
    const uint32_t* pWl_ = pWh_ + (size_t)Hh * KU;                              \
    _Pragma("unroll")                                                           \
    for (int q = 0; q < 4; ++q) {                                               \
        cpa16(dbase_ + 2 * TA_U * 4 + doffB_ + q * 16,          pWh_ + q * 4, 16u); \
        cpa16(dbase_ + 2 * TA_U * 4 + TB_U * 4 + doffB_ + q * 16, pWl_ + q * 4, 16u); \
    }                                                                           \
    asm volatile("cp.async.commit_group;" ::: "memory");                        \
} while (0)

    ISSUE(0);
    if (iters > 1) ISSUE(1);

    for (int ci = 0; ci < iters; ++ci) {
        if (ci + 1 < iters)
            asm volatile("cp.async.wait_group 1;" ::: "memory");
        else
            asm volatile("cp.async.wait_group 0;" ::: "memory");
        __syncthreads();

        const uint32_t* base = smu + (ci & 1) * STAGE2_U;
#pragma unroll
        for (int ks = 0; ks < 12; ++ks) {
            const int p = ks >> 2;
            const int kk = (ks & 3) * 8;
            const uint32_t* at = base + ((p == 1) ? TA_U : 0);
            const uint32_t* bt = base + 2 * TA_U + ((p == 2) ? TB_U : 0);
            uint32_t a[4][4];
#pragma unroll
            for (int mf = 0; mf < 4; ++mf) {
                const int r_ = wm * 64 + mf * 16 + g;
                a[mf][0] = at[(r_    ) * SMS + kk + t    ];
                a[mf][1] = at[(r_ + 8) * SMS + kk + t    ];
                a[mf][2] = at[(r_    ) * SMS + kk + t + 4];
                a[mf][3] = at[(r_ + 8) * SMS + kk + t + 4];
            }
#pragma unroll
            for (int nf = 0; nf < 8; ++nf) {
                const int nr = wn * 64 + nf * 8 + g;
                uint32_t b0 = bt[nr * SMS + kk + t];
                uint32_t b1 = bt[nr * SMS + kk + t + 4];
#pragma unroll
                for (int mf = 0; mf < 4; ++mf)
                    mma16(acc[mf][nf], a[mf], b0, b1);
            }
        }
        if (ci + 2 < iters) {
            __syncthreads();
            ISSUE(ci + 2);
        }
    }
#undef ISSUE

    // ---- epilogue
#pragma unroll
    for (int mf = 0; mf < 4; ++mf) {
#pragma unroll
        for (int half = 0; half < 2; ++half) {
            int grow = row0 + wm * 64 + mf * 16 + g + half * 8;
            if (grow >= n) continue;
            float* crow = C + (size_t)grow * 128;
#pragma unroll
            for (int nf = 0; nf < 8; ++nf) {
                int col = wn * 64 + nf * 8 + 2 * t;
                float v0 = acc[mf][nf][half * 2 + 0];
                float v1 = acc[mf][nf][half * 2 + 1];
                if (cbias) { v0 += cbias[col]; v1 += cbias[col + 1]; }
                if (relu_out) { v0 = fmaxf(v0, 0.f); v1 = fmaxf(v1, 0.f); }
                float2 v; v.x = v0; v.y = v1;
                *(float2*)(crow + col) = v;
            }
        }
    }
}

// ---------------- pooling (sorted-run accumulation, count fused) --------------
__device__ __forceinline__ void red_add_v4(float* p, float4 v) {
    asm volatile(
        "{\n\t.reg .u64 pg;\n\t"
        "cvta.to.global.u64 pg, %0;\n\t"
        "red.global.add.v4.f32 [pg], {%1,%2,%3,%4};\n\t}"
        :: "l"(p), "f"(v.x), "f"(v.y), "f"(v.z), "f"(v.w) : "memory");
}
__global__ void pool_kernel(const float* __restrict__ h, const int* __restrict__ gid) {
    int w = (blockIdx.x * blockDim.x + threadIdx.x) >> 5;
    int lane = threadIdx.x & 31;
    int n0 = w * 16;
    if (n0 >= Nn) return;
    int n1 = min(n0 + 16, Nn);
    int curg = __ldg(&gid[n0]);
    int runlen = 0;
    float4 acc = make_float4(0.f, 0.f, 0.f, 0.f);
    for (int node = n0; node < n1; ++node) {
        int g = __ldg(&gid[node]);
        if (g != curg) {
            red_add_v4(&g_pool[curg * Hh + lane * 4], acc);
            if (lane == 0) atomicAdd(&g_cnt[curg], (float)runlen);
            acc = make_float4(0.f, 0.f, 0.f, 0.f);
            runlen = 0;
            curg = g;
        }
        float4 v = *(const float4*)&h[(size_t)node * Hh + lane * 4];
        acc.x += v.x; acc.y += v.y; acc.z += v.z; acc.w += v.w;
        ++runlen;
    }
    red_add_v4(&g_pool[curg * Hh + lane * 4], acc);
    if (lane == 0) atomicAdd(&g_cnt[curg], (float)runlen);
}

// ---------------- MLP head (single block) -------------------------------------
__global__ void mlp_kernel(const float* __restrict__ Wm1, const float* __restrict__ bm1,
                           const float* __restrict__ Wm2, const float* __restrict__ bm2,
                           const float* __restrict__ Wm3, const float* __restrict__ bm3,
                           float* __restrict__ out) {
    __shared__ float z[Gg * Hh];
    int tid = threadIdx.x;   // 256
    for (int i = tid; i < Gg * Hh; i += 256)
        z[i] = g_pool[i] / fmaxf(g_cnt[i >> 7], 1.f) + g_bsum[Hh + (i & 127)];
    __syncthreads();
    float r1[32];
#pragma unroll
    for (int t = 0; t < 32; ++t) {
        int o = tid + t * 256, g = o >> 7, j = o & 127;
        float s = bm1[j];
        for (int k = 0; k < Hh; ++k) s += z[(g << 7) + k] * Wm1[k * Hh + j];
        r1[t] = fmaxf(s, 0.f);
    }
    __syncthreads();
#pragma unroll
    for (int t = 0; t < 32; ++t) z[tid + t * 256] = r1[t];
    __syncthreads();
#pragma unroll
    for (int t = 0; t < 32; ++t) {
        int o = tid + t * 256, g = o >> 7, j = o & 127;
        float s = bm2[j];
        for (int k = 0; k < Hh; ++k) s += z[(g << 7) + k] * Wm2[k * Hh + j];
        r1[t] = fmaxf(s, 0.f);
    }
    __syncthreads();
#pragma unroll
    for (int t = 0; t < 32; ++t) z[tid + t * 256] = r1[t];
    __syncthreads();
    if (tid < Gg * Cc) {
        int g = tid >> 1, c = tid & 1;
        float s = bm3[c];
        for (int k = 0; k < Hh; ++k) s += z[(g << 7) + k] * Wm3[k * Cc + c];
        out[tid] = s;
    }
}

// ---------------- launch -------------------------------------------------------
static void* symv(const void* s) {
    void* p = nullptr;
    cudaGetSymbolAddress(&p, s);
    return p;
}

extern "C" void kernel_launch(void* const* d_in, const int* in_sizes, int n_in,
                              void* d_out, int out_size) {
    const float* x    = (const float*)d_in[0];
    const int*   src  = (const int*)  d_in[1];
    const int*   dst  = (const int*)  d_in[2];
    const int*   gid  = (const int*)  d_in[3];
    const float* W_in = (const float*)d_in[4];
    const float* b_in = (const float*)d_in[5];
    const float* W1   = (const float*)d_in[6];
    const float* b1   = (const float*)d_in[7];
    const float* W2   = (const float*)d_in[8];
    const float* b2   = (const float*)d_in[9];
    const float* Wm1  = (const float*)d_in[10];
    const float* bm1  = (const float*)d_in[11];
    const float* Wm2  = (const float*)d_in[12];
    const float* bm2  = (const float*)d_in[13];
    const float* Wm3  = (const float*)d_in[14];
    const float* bm3  = (const float*)d_in[15];
    float* out = (float*)d_out;

    float*    p_h    = (float*)   symv(g_h);
    float*    p_out2 = (float*)   symv(g_out2);
    int*      p_cout = (int*)     symv(g_cout);
    int*      p_cin  = (int*)     symv(g_cin);
    float*    p_pool = (float*)   symv(g_pool);
    float*    p_cnt  = (float*)   symv(g_cnt);
    uint32_t* p_wst  = (uint32_t*)symv(g_wst);
    uint32_t* p_wtin = (uint32_t*)symv(g_wtin);
    float*    p_bsum = (float*)   symv(g_bsum);
    uint32_t* p_Ah   = (uint32_t*)symv(g_Ah);
    uint32_t* p_Al   = (uint32_t*)symv(g_Al);

    const int TB = 256;
    const int gemm_blocks = (Nn + 255) / 256;       // 391
    const int scan_blocks = (RN + 1023) / 1024;     // 391
    const int gat_blocks = (Nn * 32 + TB - 1) / TB;
    const int smem_gemm = 2 * STAGE2_U * 4;         // 221184 bytes

    cudaFuncSetAttribute(bf16_gemm_kernel,
                         cudaFuncAttributeMaxDynamicSharedMemorySize, smem_gemm);

    // side stream + fork/join events (fresh per call; correctness + capture only)
    cudaStream_t s2;
    cudaEvent_t evF, evJ;
    cudaStreamCreateWithFlags(&s2, cudaStreamNonBlocking);
    cudaEventCreateWithFlags(&evF, cudaEventDisableTiming);
    cudaEventCreateWithFlags(&evJ, cudaEventDisableTiming);

    // ---- fork: side stream builds CSR + degrees + zero pool
    cudaEventRecord(evF, 0);
    cudaStreamWaitEvent(s2, evF, 0);

    cudaMemsetAsync(p_cout, 0, (size_t)RN * sizeof(int), s2);
    cudaMemsetAsync(p_cin,  0, (size_t)RN * sizeof(int), s2);
    degree_kernel<<<(RE + TB - 1) / TB, TB, 0, s2>>>(src, dst);
    scan1_kernel<<<scan_blocks, 256, 0, s2>>>();
    scan2_kernel<<<1, 512, 0, s2>>>(scan_blocks);
    scan3_kernel<<<scan_blocks, 256, 0, s2>>>();
    cudaMemsetAsync(p_cin, 0, (size_t)RN * sizeof(int), s2);
    fill_kernel<<<(RE + TB - 1) / TB, TB, 0, s2>>>(src, dst);
    cudaMemsetAsync(p_pool, 0, (size_t)Gg * Hh * sizeof(float), s2);
    cudaMemsetAsync(p_cnt,  0, (size_t)Gg * sizeof(float), s2);
    cudaEventRecord(evJ, s2);

    // ---- main stream: weights + input layer (independent of CSR)
    wprep_kernel<<<(2 * Hh * KU_L + Hh * KU_I + TB - 1) / TB, TB>>>(W1, W2, W_in);
    bsum_kernel<<<1, 128>>>(b1, b2);
    conv_kernel<<<(Nn * KU_I + TB - 1) / TB, TB>>>(x, KU_I, p_Ah, p_Al, Nn * KU_I);
    bf16_gemm_kernel<<<gemm_blocks, 256, smem_gemm>>>(
        p_Ah, p_Al, KU_I, p_wtin, b_in, 1, p_h, Nn);

    // ---- join: gathers need both CSR (side) and h0 (main)
    cudaStreamWaitEvent(0, evJ, 0);

    // --- layer 1: gather (warp per node,relation) -> stacked GEMM
    gather_kernel<<<dim3(gat_blocks, Rr), TB>>>(p_h, p_Ah, p_Al);
    bf16_gemm_kernel<<<gemm_blocks, 256, smem_gemm>>>(
        p_Ah, p_Al, KU_L, p_wst, p_bsum, 1, p_h, Nn);

    // --- layer 2
    gather_kernel<<<dim3(gat_blocks, Rr), TB>>>(p_h, p_Ah, p_Al);
    bf16_gemm_kernel<<<gemm_blocks, 256, smem_gemm>>>(
        p_Ah, p_Al, KU_L, p_wst + (size_t)WST, nullptr, 0, p_out2, Nn);

    // --- pool + head
    pool_kernel<<<((Nn + 15) / 16 * 32 + TB - 1) / TB, TB>>>(p_out2, gid);
    mlp_kernel<<<1, TB>>>(Wm1, bm1, Wm2, bm2, Wm3, bm3, out);
}

// round 15
// speedup vs baseline: 1.0056x; 1.0056x over previous
#include <cuda_runtime.h>
#include <cuda_bf16.h>
#include <math.h>
#include <stdint.h>

// Problem constants (fixed by the reference)
#define Nn 100000
#define Ee 400000
#define Rr 4
#define Gg 64
#define INF 64
#define Hh 128
#define Cc 2
#define RN (Rr * Nn)        // 400000
#define RE (Rr * Ee)        // 1600000

#define KU_L 256            // stacked K for layer GEMMs (512 k / 2)
#define KU_I 32             // input GEMM (64 k / 2)
#define WST  (2 * Hh * KU_L)
#define WST_IN (2 * Hh * KU_I)

// ---------------- scratch (device globals; no allocation allowed) ----------
__device__ float    g_h   [(size_t)Nn * Hh];
__device__ float    g_out2[(size_t)Nn * Hh];
__device__ int      g_cout[RN];
__device__ int      g_cin [RN];
__device__ int      g_rp  [RN + 1];
__device__ int      g_bs  [512];
__device__ int      g_eidx  [RE];
__device__ float    g_escale[RE];
__device__ uint32_t g_wst   [2 * WST];
__device__ uint32_t g_wtin  [WST_IN];
__device__ float    g_bsum  [2 * Hh];
__device__ uint32_t g_Ah[(size_t)Nn * KU_L];
__device__ uint32_t g_Al[(size_t)Nn * KU_L];
__device__ float    g_pool[Gg * Hh];
__device__ float    g_cnt [Gg];

// ---------------- helpers ----------------------------------------------------
__device__ __forceinline__ uint32_t packbf_hi(float a, float b, float& ra, float& rb) {
    __nv_bfloat162 h = __floats2bfloat162_rn(a, b);
    ra = a - __bfloat162float(h.x);
    rb = b - __bfloat162float(h.y);
    return *reinterpret_cast<uint32_t*>(&h);
}
__device__ __forceinline__ uint32_t packbf(float a, float b) {
    __nv_bfloat162 h = __floats2bfloat162_rn(a, b);
    return *reinterpret_cast<uint32_t*>(&h);
}

// ---------------- degrees ----------------------------------------------------
__global__ void degree_kernel(const int* __restrict__ src, const int* __restrict__ dst) {
    int i = blockIdx.x * blockDim.x + threadIdx.x;
    if (i < RE) {
        int r = i / Ee;
        atomicAdd(&g_cout[r * Nn + src[i]], 1);
        atomicAdd(&g_cin [r * Nn + dst[i]], 1);
    }
}

// ---------------- CSR build: scan + fill --------------------------------------
__global__ void scan1_kernel() {
    __shared__ int ts[256];
    int b = blockIdx.x, t = threadIdx.x;
    int i0 = b * 1024 + t * 4;
    int v0 = (i0 + 0 < RN) ? g_cin[i0 + 0] : 0;
    int v1 = (i0 + 1 < RN) ? g_cin[i0 + 1] : 0;
    int v2 = (i0 + 2 < RN) ? g_cin[i0 + 2] : 0;
    int v3 = (i0 + 3 < RN) ? g_cin[i0 + 3] : 0;
    int tot = v0 + v1 + v2 + v3;
    ts[t] = tot;
    __syncthreads();
    for (int off = 1; off < 256; off <<= 1) {
        int x = (t >= off) ? ts[t - off] : 0;
        __syncthreads();
        ts[t] += x;
        __syncthreads();
    }
    int excl = ts[t] - tot;
    if (i0 + 0 < RN) g_rp[i0 + 0] = excl;
    if (i0 + 1 < RN) g_rp[i0 + 1] = excl + v0;
    if (i0 + 2 < RN) g_rp[i0 + 2] = excl + v0 + v1;
    if (i0 + 3 < RN) g_rp[i0 + 3] = excl + v0 + v1 + v2;
    if (t == 255) g_bs[b] = ts[255];
}
__global__ void scan2_kernel(int nb) {
    __shared__ int ts[512];
    int t = threadIdx.x;
    int v = (t < nb) ? g_bs[t] : 0;
    ts[t] = v;
    __syncthreads();
    for (int off = 1; off < 512; off <<= 1) {
        int x = (t >= off) ? ts[t - off] : 0;
        __syncthreads();
        ts[t] += x;
        __syncthreads();
    }
    g_bs[t] = ts[t] - v;
}
__global__ void scan3_kernel() {
    int b = blockIdx.x, t = threadIdx.x;
    int add = g_bs[b];
    int i0 = b * 1024 + t * 4;
#pragma unroll
    for (int q = 0; q < 4; ++q)
        if (i0 + q < RN) g_rp[i0 + q] += add;
    if (b == 0 && t == 0) g_rp[RN] = RE;
}
__global__ void fill_kernel(const int* __restrict__ src, const int* __restrict__ dst) {
    int i = blockIdx.x * blockDim.x + threadIdx.x;
    if (i >= RE) return;
    int r = i / Ee;
    int s = src[i];
    int idx = r * Nn + dst[i];
    int pos = g_rp[idx] + atomicAdd(&g_cin[idx], 1);
    g_eidx[pos] = s;
    g_escale[pos] = rsqrtf((float)max(g_cout[r * Nn + s], 1));
}

// ---------------- weight prep ---------------------------------------------------
__global__ void wprep_kernel(const float* __restrict__ W1,
                             const float* __restrict__ W2,
                             const float* __restrict__ Win) {
    int i = blockIdx.x * blockDim.x + threadIdx.x;
    const int TL = 2 * Hh * KU_L;
    if (i < TL) {
        int l = i >> 15;
        int rem = i & 32767;
        int n = rem >> 8, j = rem & 255;
        int r = j >> 6, ku = j & 63;
        const float* W = (l == 0 ? W1 : W2) + (size_t)r * Hh * Hh;
        float w0 = W[(2 * ku) * Hh + n];
        float w1 = W[(2 * ku + 1) * Hh + n];
        float r0, r1;
        uint32_t hi = packbf_hi(w0, w1, r0, r1);
        size_t base = (size_t)l * WST;
        g_wst[base + (size_t)n * KU_L + j] = hi;
        g_wst[base + (size_t)Hh * KU_L + (size_t)n * KU_L + j] = packbf(r0, r1);
    } else {
        int j = i - TL;
        if (j < Hh * KU_I) {
            int n = j >> 5, ku = j & 31;
            float w0 = Win[(2 * ku) * Hh + n];
            float w1 = Win[(2 * ku + 1) * Hh + n];
            float r0, r1;
            uint32_t hi = packbf_hi(w0, w1, r0, r1);
            g_wtin[n * KU_I + ku] = hi;
            g_wtin[Hh * KU_I + n * KU_I + ku] = packbf(r0, r1);
        }
    }
}

__global__ void bsum_kernel(const float* __restrict__ b1,
                            const float* __restrict__ b2) {
    int j = threadIdx.x;
    if (j < Hh) {
        float s1 = 0.f, s2 = 0.f;
        for (int r = 0; r < Rr; ++r) { s1 += b1[r * Hh + j]; s2 += b2[r * Hh + j]; }
        g_bsum[j] = s1; g_bsum[Hh + j] = s2;
    }
}

// ---------------- fp32 -> bf16 hi/lo planes for x -----------------------------
__global__ void conv_kernel(const float* __restrict__ src, int KU2,
                            uint32_t* __restrict__ ph, uint32_t* __restrict__ pl,
                            int total) {
    int i = blockIdx.x * blockDim.x + threadIdx.x;
    if (i >= total) return;
    int row = i / KU2, ku = i - row * KU2;
    float2 f = *(const float2*)(src + (size_t)row * (2 * KU2) + 2 * ku);
    float r0, r1;
    ph[i] = packbf_hi(f.x, f.y, r0, r1);
    pl[i] = packbf(r0, r1);
}

// ---------------- CSR gather: warp per (node, relation) ----------------------
__global__ void gather_kernel(const float* __restrict__ h,
                              uint32_t* __restrict__ Ah, uint32_t* __restrict__ Al) {
    int w = (blockIdx.x * blockDim.x + threadIdx.x) >> 5;
    int lane = threadIdx.x & 31;
    if (w >= Nn) return;
    int r = blockIdx.y;
    int idx = r * Nn + w;
    int p0 = __ldg(&g_rp[idx]);
    int p1 = __ldg(&g_rp[idx + 1]);
    float4 acc = make_float4(0.f, 0.f, 0.f, 0.f);
    int p = p0;
    for (; p + 4 <= p1; p += 4) {
        int s0 = __ldg(&g_eidx[p]);
        int s1 = __ldg(&g_eidx[p + 1]);
        int s2 = __ldg(&g_eidx[p + 2]);
        int s3 = __ldg(&g_eidx[p + 3]);
        float c0 = __ldg(&g_escale[p]);
        float c1 = __ldg(&g_escale[p + 1]);
        float c2 = __ldg(&g_escale[p + 2]);
        float c3 = __ldg(&g_escale[p + 3]);
        float4 v0 = *(const float4*)&h[(size_t)s0 * Hh + lane * 4];
        float4 v1 = *(const float4*)&h[(size_t)s1 * Hh + lane * 4];
        float4 v2 = *(const float4*)&h[(size_t)s2 * Hh + lane * 4];
        float4 v3 = *(const float4*)&h[(size_t)s3 * Hh + lane * 4];
        acc.x = fmaf(v0.x, c0, acc.x); acc.y = fmaf(v0.y, c0, acc.y);
        acc.z = fmaf(v0.z, c0, acc.z); acc.w = fmaf(v0.w, c0, acc.w);
        acc.x = fmaf(v1.x, c1, acc.x); acc.y = fmaf(v1.y, c1, acc.y);
        acc.z = fmaf(v1.z, c1, acc.z); acc.w = fmaf(v1.w, c1, acc.w);
        acc.x = fmaf(v2.x, c2, acc.x); acc.y = fmaf(v2.y, c2, acc.y);
        acc.z = fmaf(v2.z, c2, acc.z); acc.w = fmaf(v2.w, c2, acc.w);
        acc.x = fmaf(v3.x, c3, acc.x); acc.y = fmaf(v3.y, c3, acc.y);
        acc.z = fmaf(v3.z, c3, acc.z); acc.w = fmaf(v3.w, c3, acc.w);
    }
    for (; p < p1; ++p) {
        int s = __ldg(&g_eidx[p]);
        float sc = __ldg(&g_escale[p]);
        float4 v = *(const float4*)&h[(size_t)s * Hh + lane * 4];
        acc.x = fmaf(v.x, sc, acc.x);
        acc.y = fmaf(v.y, sc, acc.y);
        acc.z = fmaf(v.z, sc, acc.z);
        acc.w = fmaf(v.w, sc, acc.w);
    }
    float ri = rsqrtf((float)max(p1 - p0, 1));   // deg_in from CSR row extent
    acc.x *= ri; acc.y *= ri; acc.z *= ri; acc.w *= ri;
    float r0, r1, r2, r3;
    uint32_t h0 = packbf_hi(acc.x, acc.y, r0, r1);
    uint32_t h1 = packbf_hi(acc.z, acc.w, r2, r3);
    size_t base = (size_t)w * KU_L + r * 64 + 2 * lane;
    *(uint2*)&Ah[base] = make_uint2(h0, h1);
    *(uint2*)&Al[base] = make_uint2(packbf(r0, r1), packbf(r2, r3));
}

// ---------------- bf16 3-pass GEMM: 512 threads, CTA 256x128, warp 32x64 -----
// 16 warps in 8(M)x2(N); acc 64 regs/thread. 2-stage cp.async, 221 KB smem.
#define SMS 36
#define TA_U (256 * SMS)
#define TB_U (128 * SMS)
#define STAGE2_U (2 * TA_U + 2 * TB_U)   // 27648 u32 = 110592 B per stage

__device__ __forceinline__ void mma16(float* c, const uint32_t* a,
                                      uint32_t b0, uint32_t b1) {
    asm volatile(
        "mma.sync.aligned.m16n8k16.row.col.f32.bf16.bf16.f32 "
        "{%0,%1,%2,%3}, {%4,%5,%6,%7}, {%8,%9}, {%0,%1,%2,%3};"
        : "+f"(c[0]), "+f"(c[1]), "+f"(c[2]), "+f"(c[3])
        : "r"(a[0]), "r"(a[1]), "r"(a[2]), "r"(a[3]), "r"(b0), "r"(b1));
}
__device__ __forceinline__ void cpa16(uint32_t daddr, const uint32_t* src, uint32_t nbytes) {
    asm volatile("cp.async.cg.shared.global [%0], [%1], 16, %2;"
                 :: "r"(daddr), "l"(src), "r"(nbytes) : "memory");
}

__global__ void __launch_bounds__(512)
bf16_gemm_kernel(const uint32_t* __restrict__ Ah, const uint32_t* __restrict__ Al,
                 int KU,
                 const uint32_t* __restrict__ Wp,
                 const float* __restrict__ cbias,   // nullable
                 int relu_out,
                 float* __restrict__ C, int n) {
    extern __shared__ uint32_t smu[];

    const int tid = threadIdx.x;
    const int lane = tid & 31, warp = tid >> 5;   // 16 warps
    const int wm = warp >> 1, wn = warp & 1;      // wm 0..7 (32 rows), wn 0..1
    const int g = lane >> 2, t = lane & 3;
    const int row0 = blockIdx.x * 256;
    const int iters = KU >> 5;

    // A staging: 2 threads per row (256 rows), 16 u32 each per plane
    const int sra = tid >> 1;
    const int sca = (tid & 1) * 16;
    const int grow_s = row0 + sra;
    const int arow = (grow_s < n) ? grow_s : (n - 1);
    const uint32_t avalid = (grow_s < n) ? 16u : 0u;
    // B staging: 4 threads per row (128 rows), 8 u32 each per plane
    const int srb = tid >> 2;
    const int scb = (tid & 3) * 8;

    uint32_t smbase = (uint32_t)__cvta_generic_to_shared(smu);

    float acc[2][8][4];
#pragma unroll
    for (int mf = 0; mf < 2; ++mf)
#pragma unroll
        for (int nf = 0; nf < 8; ++nf)
#pragma unroll
            for (int q = 0; q < 4; ++q) acc[mf][nf][q] = 0.f;

#define ISSUE(CI) do {                                                          \
    const int uc_ = (CI) * 32;                                                  \
    const uint32_t dbase_ = smbase + ((CI) & 1) * (STAGE2_U * 4);               \
    const uint32_t doffA_ = (uint32_t)(sra * SMS + sca) * 4;                    \
    const uint32_t* pAh_ = Ah + (size_t)arow * KU + uc_ + sca;                  \
    const uint32_t* pAl_ = Al + (size_t)arow * KU + uc_ + sca;                  \
    _Pragma("unroll")                                                           \
    for (int q = 0; q < 4; ++q) {                                               \
        cpa16(dbase_ + doffA_ + q * 16,            pAh_ + q * 4, avalid);       \
        cpa16(dbase_ + TA_U * 4 + doffA_ + q * 16, pAl_ + q * 4, avalid);       \
    }                                                                           \
    const uint32_t doffB_ = (uint32_t)(srb * SMS + scb) * 4;                    \
    const uint32_t* pWh_ = Wp + (size_t)srb * KU + uc_ + scb;                   \
    const uint32_t* pWl_ = pWh_ + (size_t)Hh * KU;                              \
    _Pragma("unroll")                                                           \
    for (int q = 0; q < 2; ++q) {                                               \
        cpa16(dbase_ + 2 * TA_U * 4 + doffB_ + q * 16,            pWh_ + q * 4, 16u); \
        cpa16(dbase_ + 2 * TA_U * 4 + TB_U * 4 + doffB_ + q * 16, pWl_ + q * 4, 16u); \
    }                                                                           \
    asm volatile("cp.async.commit_group;" ::: "memory");                        \
} while (0)

    ISSUE(0);
    if (iters > 1) ISSUE(1);

    for (int ci = 0; ci < iters; ++ci) {
        if (ci + 1 < iters)
            asm volatile("cp.async.wait_group 1;" ::: "memory");
        else
            asm volatile("cp.async.wait_group 0;" ::: "memory");
        __syncthreads();

        const uint32_t* base = smu + (ci & 1) * STAGE2_U;
#pragma unroll
        for (int ks = 0; ks < 12; ++ks) {
            const int p = ks >> 2;
            const int kk = (ks & 3) * 8;
            const uint32_t* at = base + ((p == 1) ? TA_U : 0);
            const uint32_t* bt = base + 2 * TA_U + ((p == 2) ? TB_U : 0);
            uint32_t a[2][4];
#pragma unroll
            for (int mf = 0; mf < 2; ++mf) {
                const int r_ = wm * 32 + mf * 16 + g;
                a[mf][0] = at[(r_    ) * SMS + kk + t    ];
                a[mf][1] = at[(r_ + 8) * SMS + kk + t    ];
                a[mf][2] = at[(r_    ) * SMS + kk + t + 4];
                a[mf][3] = at[(r_ + 8) * SMS + kk + t + 4];
            }
#pragma unroll
            for (int nf = 0; nf < 8; ++nf) {
                const int nr = wn * 64 + nf * 8 + g;
                uint32_t b0 = bt[nr * SMS + kk + t];
                uint32_t b1 = bt[nr * SMS + kk + t + 4];
                mma16(acc[0][nf], a[0], b0, b1);
                mma16(acc[1][nf], a[1], b0, b1);
            }
        }
        if (ci + 2 < iters) {
            __syncthreads();
            ISSUE(ci + 2);
        }
    }
#undef ISSUE

    // ---- epilogue
#pragma unroll
    for (int mf = 0; mf < 2; ++mf) {
#pragma unroll
        for (int half = 0; half < 2; ++half) {
            int grow = row0 + wm * 32 + mf * 16 + g + half * 8;
            if (grow >= n) continue;
            float* crow = C + (size_t)grow * 128;
#pragma unroll
            for (int nf = 0; nf < 8; ++nf) {
                int col = wn * 64 + nf * 8 + 2 * t;
                float v0 = acc[mf][nf][half * 2 + 0];
                float v1 = acc[mf][nf][half * 2 + 1];
                if (cbias) { v0 += cbias[col]; v1 += cbias[col + 1]; }
                if (relu_out) { v0 = fmaxf(v0, 0.f); v1 = fmaxf(v1, 0.f); }
                float2 v; v.x = v0; v.y = v1;
                *(float2*)(crow + col) = v;
            }
        }
    }
}

// ---------------- pooling (sorted-run accumulation, count fused) --------------
__device__ __forceinline__ void red_add_v4(float* p, float4 v) {
    asm volatile(
        "{\n\t.reg .u64 pg;\n\t"
        "cvta.to.global.u64 pg, %0;\n\t"
        "red.global.add.v4.f32 [pg], {%1,%2,%3,%4};\n\t}"
        :: "l"(p), "f"(v.x), "f"(v.y), "f"(v.z), "f"(v.w) : "memory");
}
__global__ void pool_kernel(const float* __restrict__ h, const int* __restrict__ gid) {
    int w = (blockIdx.x * blockDim.x + threadIdx.x) >> 5;
    int lane = threadIdx.x & 31;
    int n0 = w * 16;
    if (n0 >= Nn) return;
    int n1 = min(n0 + 16, Nn);
    int curg = __ldg(&gid[n0]);
    int runlen = 0;
    float4 acc = make_float4(0.f, 0.f, 0.f, 0.f);
    for (int node = n0; node < n1; ++node) {
        int g = __ldg(&gid[node]);
        if (g != curg) {
            red_add_v4(&g_pool[curg * Hh + lane * 4], acc);
            if (lane == 0) atomicAdd(&g_cnt[curg], (float)runlen);
            acc = make_float4(0.f, 0.f, 0.f, 0.f);
            runlen = 0;
            curg = g;
        }
        float4 v = *(const float4*)&h[(size_t)node * Hh + lane * 4];
        acc.x += v.x; acc.y += v.y; acc.z += v.z; acc.w += v.w;
        ++runlen;
    }
    red_add_v4(&g_pool[curg * Hh + lane * 4], acc);
    if (lane == 0) atomicAdd(&g_cnt[curg], (float)runlen);
}

// ---------------- MLP head (single block) -------------------------------------
__global__ void mlp_kernel(const float* __restrict__ Wm1, const float* __restrict__ bm1,
                           const float* __restrict__ Wm2, const float* __restrict__ bm2,
                           const float* __restrict__ Wm3, const float* __restrict__ bm3,
                           float* __restrict__ out) {
    __shared__ float z[Gg * Hh];
    int tid = threadIdx.x;   // 256
    for (int i = tid; i < Gg * Hh; i += 256)
        z[i] = g_pool[i] / fmaxf(g_cnt[i >> 7], 1.f) + g_bsum[Hh + (i & 127)];
    __syncthreads();
    float r1[32];
#pragma unroll
    for (int t = 0; t < 32; ++t) {
        int o = tid + t * 256, g = o >> 7, j = o & 127;
        float s = bm1[j];
        for (int k = 0; k < Hh; ++k) s += z[(g << 7) + k] * Wm1[k * Hh + j];
        r1[t] = fmaxf(s, 0.f);
    }
    __syncthreads();
#pragma unroll
    for (int t = 0; t < 32; ++t) z[tid + t * 256] = r1[t];
    __syncthreads();
#pragma unroll
    for (int t = 0; t < 32; ++t) {
        int o = tid + t * 256, g = o >> 7, j = o & 127;
        float s = bm2[j];
        for (int k = 0; k < Hh; ++k) s += z[(g << 7) + k] * Wm2[k * Hh + j];
        r1[t] = fmaxf(s, 0.f);
    }
    __syncthreads();
#pragma unroll
    for (int t = 0; t < 32; ++t) z[tid + t * 256] = r1[t];
    __syncthreads();
    if (tid < Gg * Cc) {
        int g = tid >> 1, c = tid & 1;
        float s = bm3[c];
        for (int k = 0; k < Hh; ++k) s += z[(g << 7) + k] * Wm3[k * Cc + c];
        out[tid] = s;
    }
}

// ---------------- launch -------------------------------------------------------
static void* symv(const void* s) {
    void* p = nullptr;
    cudaGetSymbolAddress(&p, s);
    return p;
}

extern "C" void kernel_launch(void* const* d_in, const int* in_sizes, int n_in,
                              void* d_out, int out_size) {
    const float* x    = (const float*)d_in[0];
    const int*   src  = (const int*)  d_in[1];
    const int*   dst  = (const int*)  d_in[2];
    const int*   gid  = (const int*)  d_in[3];
    const float* W_in = (const float*)d_in[4];
    const float* b_in = (const float*)d_in[5];
    const float* W1   = (const float*)d_in[6];
    const float* b1   = (const float*)d_in[7];
    const float* W2   = (const float*)d_in[8];
    const float* b2   = (const float*)d_in[9];
    const float* Wm1  = (const float*)d_in[10];
    const float* bm1  = (const float*)d_in[11];
    const float* Wm2  = (const float*)d_in[12];
    const float* bm2  = (const float*)d_in[13];
    const float* Wm3  = (const float*)d_in[14];
    const float* bm3  = (const float*)d_in[15];
    float* out = (float*)d_out;

    float*    p_h    = (float*)   symv(g_h);
    float*    p_out2 = (float*)   symv(g_out2);
    int*      p_cout = (int*)     symv(g_cout);
    int*      p_cin  = (int*)     symv(g_cin);
    float*    p_pool = (float*)   symv(g_pool);
    float*    p_cnt  = (float*)   symv(g_cnt);
    uint32_t* p_wst  = (uint32_t*)symv(g_wst);
    uint32_t* p_wtin = (uint32_t*)symv(g_wtin);
    float*    p_bsum = (float*)   symv(g_bsum);
    uint32_t* p_Ah   = (uint32_t*)symv(g_Ah);
    uint32_t* p_Al   = (uint32_t*)symv(g_Al);

    const int TB = 256;
    const int gemm_blocks = (Nn + 255) / 256;       // 391
    const int scan_blocks = (RN + 1023) / 1024;     // 391
    const int gat_blocks = (Nn * 32 + TB - 1) / TB;
    const int smem_gemm = 2 * STAGE2_U * 4;         // 221184 bytes

    cudaFuncSetAttribute(bf16_gemm_kernel,
                         cudaFuncAttributeMaxDynamicSharedMemorySize, smem_gemm);

    // side stream + fork/join events (fresh per call; correctness + capture only)
    cudaStream_t s2;
    cudaEvent_t evF, evJ;
    cudaStreamCreateWithFlags(&s2, cudaStreamNonBlocking);
    cudaEventCreateWithFlags(&evF, cudaEventDisableTiming);
    cudaEventCreateWithFlags(&evJ, cudaEventDisableTiming);

    // ---- fork: side stream builds CSR + degrees + zero pool
    cudaEventRecord(evF, 0);
    cudaStreamWaitEvent(s2, evF, 0);

    cudaMemsetAsync(p_cout, 0, (size_t)RN * sizeof(int), s2);
    cudaMemsetAsync(p_cin,  0, (size_t)RN * sizeof(int), s2);
    degree_kernel<<<(RE + TB - 1) / TB, TB, 0, s2>>>(src, dst);
    scan1_kernel<<<scan_blocks, 256, 0, s2>>>();
    scan2_kernel<<<1, 512, 0, s2>>>(scan_blocks);
    scan3_kernel<<<scan_blocks, 256, 0, s2>>>();
    cudaMemsetAsync(p_cin, 0, (size_t)RN * sizeof(int), s2);
    fill_kernel<<<(RE + TB - 1) / TB, TB, 0, s2>>>(src, dst);
    cudaMemsetAsync(p_pool, 0, (size_t)Gg * Hh * sizeof(float), s2);
    cudaMemsetAsync(p_cnt,  0, (size_t)Gg * sizeof(float), s2);
    cudaEventRecord(evJ, s2);

    // ---- main stream: weights + input layer (independent of CSR)
    wprep_kernel<<<(2 * Hh * KU_L + Hh * KU_I + TB - 1) / TB, TB>>>(W1, W2, W_in);
    bsum_kernel<<<1, 128>>>(b1, b2);
    conv_kernel<<<(Nn * KU_I + TB - 1) / TB, TB>>>(x, KU_I, p_Ah, p_Al, Nn * KU_I);
    bf16_gemm_kernel<<<gemm_blocks, 512, smem_gemm>>>(
        p_Ah, p_Al, KU_I, p_wtin, b_in, 1, p_h, Nn);

    // ---- join: gathers need both CSR (side) and h0 (main)
    cudaStreamWaitEvent(0, evJ, 0);

    // --- layer 1: gather (warp per node,relation) -> stacked GEMM
    gather_kernel<<<dim3(gat_blocks, Rr), TB>>>(p_h, p_Ah, p_Al);
    bf16_gemm_kernel<<<gemm_blocks, 512, smem_gemm>>>(
        p_Ah, p_Al, KU_L, p_wst, p_bsum, 1, p_h, Nn);

    // --- layer 2
    gather_kernel<<<dim3(gat_blocks, Rr), TB>>>(p_h, p_Ah, p_Al);
    bf16_gemm_kernel<<<gemm_blocks, 512, smem_gemm>>>(
        p_Ah, p_Al, KU_L, p_wst + (size_t)WST, nullptr, 0, p_out2, Nn);

    // --- pool + head
    pool_kernel<<<((Nn + 15) / 16 * 32 + TB - 1) / TB, TB>>>(p_out2, gid);
    mlp_kernel<<<1, TB>>>(Wm1, bm1, Wm2, bm2, Wm3, bm3, out);
}

// round 16
// speedup vs baseline: 1.0661x; 1.0602x over previous
#include <cuda_runtime.h>
#include <cuda_bf16.h>
#include <math.h>
#include <stdint.h>

// Problem constants (fixed by the reference)
#define Nn 100000
#define Ee 400000
#define Rr 4
#define Gg 64
#define INF 64
#define Hh 128
#define Cc 2
#define RN (Rr * Nn)        // 400000
#define RE (Rr * Ee)        // 1600000

#define KU_L 256            // stacked K for layer GEMMs (512 k / 2)
#define KU_I 32             // input GEMM (64 k / 2)
#define WST  (2 * Hh * KU_L)
#define WST_IN (2 * Hh * KU_I)

// ---------------- scratch (device globals; no allocation allowed) ----------
__device__ float    g_h   [(size_t)Nn * Hh];
__device__ float    g_out2[(size_t)Nn * Hh];
__device__ int      g_cout[RN];
__device__ int      g_cin [RN];
__device__ int      g_rp  [RN + 1];
__device__ int      g_bs  [512];
__device__ int2     g_edge[RE];          // {src index, scale bits} interleaved
__device__ uint32_t g_wst   [2 * WST];
__device__ uint32_t g_wtin  [WST_IN];
__device__ float    g_bsum  [2 * Hh];
__device__ uint32_t g_Ah[(size_t)Nn * KU_L];
__device__ uint32_t g_Al[(size_t)Nn * KU_L];
__device__ float    g_pool[Gg * Hh];
__device__ float    g_cnt [Gg];

// ---------------- helpers ----------------------------------------------------
__device__ __forceinline__ uint32_t packbf_hi(float a, float b, float& ra, float& rb) {
    __nv_bfloat162 h = __floats2bfloat162_rn(a, b);
    ra = a - __bfloat162float(h.x);
    rb = b - __bfloat162float(h.y);
    return *reinterpret_cast<uint32_t*>(&h);
}
__device__ __forceinline__ uint32_t packbf(float a, float b) {
    __nv_bfloat162 h = __floats2bfloat162_rn(a, b);
    return *reinterpret_cast<uint32_t*>(&h);
}

// ---------------- degrees ----------------------------------------------------
__global__ void degree_kernel(const int* __restrict__ src, const int* __restrict__ dst) {
    int i = blockIdx.x * blockDim.x + threadIdx.x;
    if (i < RE) {
        int r = i / Ee;
        atomicAdd(&g_cout[r * Nn + src[i]], 1);
        atomicAdd(&g_cin [r * Nn + dst[i]], 1);
    }
}

// ---------------- CSR build: scan + fill --------------------------------------
__global__ void scan1_kernel() {
    __shared__ int ts[256];
    int b = blockIdx.x, t = threadIdx.x;
    int i0 = b * 1024 + t * 4;
    int v0 = (i0 + 0 < RN) ? g_cin[i0 + 0] : 0;
    int v1 = (i0 + 1 < RN) ? g_cin[i0 + 1] : 0;
    int v2 = (i0 + 2 < RN) ? g_cin[i0 + 2] : 0;
    int v3 = (i0 + 3 < RN) ? g_cin[i0 + 3] : 0;
    int tot = v0 + v1 + v2 + v3;
    ts[t] = tot;
    __syncthreads();
    for (int off = 1; off < 256; off <<= 1) {
        int x = (t >= off) ? ts[t - off] : 0;
        __syncthreads();
        ts[t] += x;
        __syncthreads();
    }
    int excl = ts[t] - tot;
    if (i0 + 0 < RN) g_rp[i0 + 0] = excl;
    if (i0 + 1 < RN) g_rp[i0 + 1] = excl + v0;
    if (i0 + 2 < RN) g_rp[i0 + 2] = excl + v0 + v1;
    if (i0 + 3 < RN) g_rp[i0 + 3] = excl + v0 + v1 + v2;
    if (t == 255) g_bs[b] = ts[255];
}
__global__ void scan2_kernel(int nb) {
    __shared__ int ts[512];
    int t = threadIdx.x;
    int v = (t < nb) ? g_bs[t] : 0;
    ts[t] = v;
    __syncthreads();
    for (int off = 1; off < 512; off <<= 1) {
        int x = (t >= off) ? ts[t - off] : 0;
        __syncthreads();
        ts[t] += x;
        __syncthreads();
    }
    g_bs[t] = ts[t] - v;
}
__global__ void scan3_kernel() {
    int b = blockIdx.x, t = threadIdx.x;
    int add = g_bs[b];
    int i0 = b * 1024 + t * 4;
#pragma unroll
    for (int q = 0; q < 4; ++q)
        if (i0 + q < RN) g_rp[i0 + q] += add;
    if (b == 0 && t == 0) g_rp[RN] = RE;
}
__global__ void fill_kernel(const int* __restrict__ src, const int* __restrict__ dst) {
    int i = blockIdx.x * blockDim.x + threadIdx.x;
    if (i >= RE) return;
    int r = i / Ee;
    int s = src[i];
    int idx = r * Nn + dst[i];
    int pos = g_rp[idx] + atomicAdd(&g_cin[idx], 1);
    float sc = rsqrtf((float)max(g_cout[r * Nn + s], 1));
    g_edge[pos] = make_int2(s, __float_as_int(sc));
}

// ---------------- weight prep ---------------------------------------------------
__global__ void wprep_kernel(const float* __restrict__ W1,
                             const float* __restrict__ W2,
                             const float* __restrict__ Win) {
    int i = blockIdx.x * blockDim.x + threadIdx.x;
    const int TL = 2 * Hh * KU_L;
    if (i < TL) {
        int l = i >> 15;
        int rem = i & 32767;
        int n = rem >> 8, j = rem & 255;
        int r = j >> 6, ku = j & 63;
        const float* W = (l == 0 ? W1 : W2) + (size_t)r * Hh * Hh;
        float w0 = W[(2 * ku) * Hh + n];
        float w1 = W[(2 * ku + 1) * Hh + n];
        float r0, r1;
        uint32_t hi = packbf_hi(w0, w1, r0, r1);
        size_t base = (size_t)l * WST;
        g_wst[base + (size_t)n * KU_L + j] = hi;
        g_wst[base + (size_t)Hh * KU_L + (size_t)n * KU_L + j] = packbf(r0, r1);
    } else {
        int j = i - TL;
        if (j < Hh * KU_I) {
            int n = j >> 5, ku = j & 31;
            float w0 = Win[(2 * ku) * Hh + n];
            float w1 = Win[(2 * ku + 1) * Hh + n];
            float r0, r1;
            uint32_t hi = packbf_hi(w0, w1, r0, r1);
            g_wtin[n * KU_I + ku] = hi;
            g_wtin[Hh * KU_I + n * KU_I + ku] = packbf(r0, r1);
        }
    }
}

__global__ void bsum_kernel(const float* __restrict__ b1,
                            const float* __restrict__ b2) {
    int j = threadIdx.x;
    if (j < Hh) {
        float s1 = 0.f, s2 = 0.f;
        for (int r = 0; r < Rr; ++r) { s1 += b1[r * Hh + j]; s2 += b2[r * Hh + j]; }
        g_bsum[j] = s1; g_bsum[Hh + j] = s2;
    }
}

// ---------------- fp32 -> bf16 hi/lo planes for x -----------------------------
__global__ void conv_kernel(const float* __restrict__ src, int KU2,
                            uint32_t* __restrict__ ph, uint32_t* __restrict__ pl,
                            int total) {
    int i = blockIdx.x * blockDim.x + threadIdx.x;
    if (i >= total) return;
    int row = i / KU2, ku = i - row * KU2;
    float2 f = *(const float2*)(src + (size_t)row * (2 * KU2) + 2 * ku);
    float r0, r1;
    ph[i] = packbf_hi(f.x, f.y, r0, r1);
    pl[i] = packbf(r0, r1);
}

// ---------------- CSR gather: warp per (node, relation) ----------------------
__global__ void gather_kernel(const float* __restrict__ h,
                              uint32_t* __restrict__ Ah, uint32_t* __restrict__ Al) {
    int w = (blockIdx.x * blockDim.x + threadIdx.x) >> 5;
    int lane = threadIdx.x & 31;
    if (w >= Nn) return;
    int r = blockIdx.y;
    int idx = r * Nn + w;
    int p0 = __ldg(&g_rp[idx]);
    int p1 = __ldg(&g_rp[idx + 1]);
    float4 acc = make_float4(0.f, 0.f, 0.f, 0.f);
    int p = p0;
    for (; p + 4 <= p1; p += 4) {
        int2 e0 = __ldg(&g_edge[p]);
        int2 e1 = __ldg(&g_edge[p + 1]);
        int2 e2 = __ldg(&g_edge[p + 2]);
        int2 e3 = __ldg(&g_edge[p + 3]);
        float c0 = __int_as_float(e0.y);
        float c1 = __int_as_float(e1.y);
        float c2 = __int_as_float(e2.y);
        float c3 = __int_as_float(e3.y);
        float4 v0 = *(const float4*)&h[(size_t)e0.x * Hh + lane * 4];
        float4 v1 = *(const float4*)&h[(size_t)e1.x * Hh + lane * 4];
        float4 v2 = *(const float4*)&h[(size_t)e2.x * Hh + lane * 4];
        float4 v3 = *(const float4*)&h[(size_t)e3.x * Hh + lane * 4];
        acc.x = fmaf(v0.x, c0, acc.x); acc.y = fmaf(v0.y, c0, acc.y);
        acc.z = fmaf(v0.z, c0, acc.z); acc.w = fmaf(v0.w, c0, acc.w);
        acc.x = fmaf(v1.x, c1, acc.x); acc.y = fmaf(v1.y, c1, acc.y);
        acc.z = fmaf(v1.z, c1, acc.z); acc.w = fmaf(v1.w, c1, acc.w);
        acc.x = fmaf(v2.x, c2, acc.x); acc.y = fmaf(v2.y, c2, acc.y);
        acc.z = fmaf(v2.z, c2, acc.z); acc.w = fmaf(v2.w, c2, acc.w);
        acc.x = fmaf(v3.x, c3, acc.x); acc.y = fmaf(v3.y, c3, acc.y);
        acc.z = fmaf(v3.z, c3, acc.z); acc.w = fmaf(v3.w, c3, acc.w);
    }
    for (; p < p1; ++p) {
        int2 e = __ldg(&g_edge[p]);
        float sc = __int_as_float(e.y);
        float4 v = *(const float4*)&h[(size_t)e.x * Hh + lane * 4];
        acc.x = fmaf(v.x, sc, acc.x);
        acc.y = fmaf(v.y, sc, acc.y);
        acc.z = fmaf(v.z, sc, acc.z);
        acc.w = fmaf(v.w, sc, acc.w);
    }
    float ri = rsqrtf((float)max(p1 - p0, 1));   // deg_in from CSR row extent
    acc.x *= ri; acc.y *= ri; acc.z *= ri; acc.w *= ri;
    float r0, r1, r2, r3;
    uint32_t h0 = packbf_hi(acc.x, acc.y, r0, r1);
    uint32_t h1 = packbf_hi(acc.z, acc.w, r2, r3);
    size_t base = (size_t)w * KU_L + r * 64 + 2 * lane;
    *(uint2*)&Ah[base] = make_uint2(h0, h1);
    *(uint2*)&Al[base] = make_uint2(packbf(r0, r1), packbf(r2, r3));
}

// ---------------- bf16 3-pass GEMM: 512 threads, 3-stage cp.async (R13) ------
#define SMS 36
#define TILE_U (128 * SMS)
#define STAGE_U (4 * TILE_U)

__device__ __forceinline__ void mma16(float* c, const uint32_t* a,
                                      uint32_t b0, uint32_t b1) {
    asm volatile(
        "mma.sync.aligned.m16n8k16.row.col.f32.bf16.bf16.f32 "
        "{%0,%1,%2,%3}, {%4,%5,%6,%7}, {%8,%9}, {%0,%1,%2,%3};"
        : "+f"(c[0]), "+f"(c[1]), "+f"(c[2]), "+f"(c[3])
        : "r"(a[0]), "r"(a[1]), "r"(a[2]), "r"(a[3]), "r"(b0), "r"(b1));
}
__device__ __forceinline__ void cpa16(uint32_t daddr, const uint32_t* src, uint32_t nbytes) {
    asm volatile("cp.async.cg.shared.global [%0], [%1], 16, %2;"
                 :: "r"(daddr), "l"(src), "r"(nbytes) : "memory");
}

__global__ void __launch_bounds__(512)
bf16_gemm_kernel(const uint32_t* __restrict__ Ah, const uint32_t* __restrict__ Al,
                 int KU,
                 const uint32_t* __restrict__ Wp,
                 const float* __restrict__ cbias,   // nullable
                 int relu_out,
                 float* __restrict__ C, int n) {
    extern __shared__ uint32_t smu[];

    const int tid = threadIdx.x;
    const int lane = tid & 31, warp = tid >> 5;   // 16 warps
    const int wm = warp >> 1, wn = warp & 1;      // wm 0..7 (16 rows), wn 0..1
    const int g = lane >> 2, t = lane & 3;
    const int row0 = blockIdx.x * 128;
    const int iters = KU >> 5;

    const int sr = tid >> 2;            // 0..127
    const int sc = (tid & 3) * 8;       // 0,8,16,24
    const int grow_s = row0 + sr;
    const int arow = (grow_s < n) ? grow_s : (n - 1);
    const uint32_t avalid = (grow_s < n) ? 16u : 0u;

    uint32_t smbase = (uint32_t)__cvta_generic_to_shared(smu);

    float acc[8][4];
#pragma unroll
    for (int nf = 0; nf < 8; ++nf)
#pragma unroll
        for (int q = 0; q < 4; ++q) acc[nf][q] = 0.f;

#define ISSUE(CI) do {                                                         \
    const int uc_ = (CI) * 32 + sc;                                            \
    const uint32_t dbase_ = smbase + ((CI) % 3) * (STAGE_U * 4);               \
    const uint32_t doff_ = (sr * SMS + sc) * 4;                                \
    const uint32_t* pAh_ = Ah + (size_t)arow * KU + uc_;                       \
    const uint32_t* pAl_ = Al + (size_t)arow * KU + uc_;                       \
    const uint32_t* pWh_ = Wp + (size_t)sr * KU + uc_;                         \
    const uint32_t* pWl_ = pWh_ + (size_t)Hh * KU;                             \
    _Pragma("unroll")                                                          \
    for (int q = 0; q < 2; ++q) {                                              \
        cpa16(dbase_ + doff_ + q * 16,                  pAh_ + q * 4, avalid); \
        cpa16(dbase_ + TILE_U * 4 + doff_ + q * 16,     pAl_ + q * 4, avalid); \
        cpa16(dbase_ + 2 * TILE_U * 4 + doff_ + q * 16, pWh_ + q * 4, 16u);    \
        cpa16(dbase_ + 3 * TILE_U * 4 + doff_ + q * 16, pWl_ + q * 4, 16u);    \
    }                                                                          \
    asm volatile("cp.async.commit_group;" ::: "memory");                       \
} while (0)

    ISSUE(0);
    if (iters > 1) ISSUE(1);

    for (int ci = 0; ci < iters; ++ci) {
        if (ci + 1 < iters)
            asm volatile("cp.async.wait_group 1;" ::: "memory");
        else
            asm volatile("cp.async.wait_group 0;" ::: "memory");
        __syncthreads();
        if (ci + 2 < iters) ISSUE(ci + 2);

        const uint32_t* base = smu + (ci % 3) * STAGE_U;
#pragma unroll
        for (int ks = 0; ks < 12; ++ks) {
            const int p = ks >> 2;
            const int kk = (ks & 3) * 8;
            const uint32_t* at = base + ((p == 1) ? TILE_U : 0);
            const uint32_t* bt = base + 2 * TILE_U + ((p == 2) ? TILE_U : 0);
            const int r_ = wm * 16 + g;
            uint32_t a[4];
            a[0] = at[(r_    ) * SMS + kk + t    ];
            a[1] = at[(r_ + 8) * SMS + kk + t    ];
            a[2] = at[(r_    ) * SMS + kk + t + 4];
            a[3] = at[(r_ + 8) * SMS + kk + t + 4];
#pragma unroll
            for (int nf = 0; nf < 8; ++nf) {
                int nr = wn * 64 + nf * 8 + g;
                uint32_t b0 = bt[nr * SMS + kk + t];
                uint32_t b1 = bt[nr * SMS + kk + t + 4];
                mma16(acc[nf], a, b0, b1);
            }
        }
    }
#undef ISSUE

    // ---- epilogue
#pragma unroll
    for (int half = 0; half < 2; ++half) {
        int grow = row0 + wm * 16 + g + half * 8;
        if (grow >= n) continue;
        float* crow = C + (size_t)grow * 128;
#pragma unroll
        for (int nf = 0; nf < 8; ++nf) {
            int col = wn * 64 + nf * 8 + 2 * t;
            float v0 = acc[nf][half * 2 + 0];
            float v1 = acc[nf][half * 2 + 1];
            if (cbias) { v0 += cbias[col]; v1 += cbias[col + 1]; }
            if (relu_out) { v0 = fmaxf(v0, 0.f); v1 = fmaxf(v1, 0.f); }
            float2 v; v.x = v0; v.y = v1;
            *(float2*)(crow + col) = v;
        }
    }
}

// ---------------- pooling (sorted-run accumulation, count fused) --------------
__device__ __forceinline__ void red_add_v4(float* p, float4 v) {
    asm volatile(
        "{\n\t.reg .u64 pg;\n\t"
        "cvta.to.global.u64 pg, %0;\n\t"
        "red.global.add.v4.f32 [pg], {%1,%2,%3,%4};\n\t}"
        :: "l"(p), "f"(v.x), "f"(v.y), "f"(v.z), "f"(v.w) : "memory");
}
__global__ void pool_kernel(const float* __restrict__ h, const int* __restrict__ gid) {
    int w = (blockIdx.x * blockDim.x + threadIdx.x) >> 5;
    int lane = threadIdx.x & 31;
    int n0 = w * 16;
    if (n0 >= Nn) return;
    int n1 = min(n0 + 16, Nn);
    int curg = __ldg(&gid[n0]);
    int runlen = 0;
    float4 acc = make_float4(0.f, 0.f, 0.f, 0.f);
    for (int node = n0; node < n1; ++node) {
        int g = __ldg(&gid[node]);
        if (g != curg) {
            red_add_v4(&g_pool[curg * Hh + lane * 4], acc);
            if (lane == 0) atomicAdd(&g_cnt[curg], (float)runlen);
            acc = make_float4(0.f, 0.f, 0.f, 0.f);
            runlen = 0;
            curg = g;
        }
        float4 v = *(const float4*)&h[(size_t)node * Hh + lane * 4];
        acc.x += v.x; acc.y += v.y; acc.z += v.z; acc.w += v.w;
        ++runlen;
    }
    red_add_v4(&g_pool[curg * Hh + lane * 4], acc);
    if (lane == 0) atomicAdd(&g_cnt[curg], (float)runlen);
}

// ---------------- MLP head (single block) -------------------------------------
__global__ void mlp_kernel(const float* __restrict__ Wm1, const float* __restrict__ bm1,
                           const float* __restrict__ Wm2, const float* __restrict__ bm2,
                           const float* __restrict__ Wm3, const float* __restrict__ bm3,
                           float* __restrict__ out) {
    __shared__ float z[Gg * Hh];
    int tid = threadIdx.x;   // 256
    for (int i = tid; i < Gg * Hh; i += 256)
        z[i] = g_pool[i] / fmaxf(g_cnt[i >> 7], 1.f) + g_bsum[Hh + (i & 127)];
    __syncthreads();
    float r1[32];
#pragma unroll
    for (int t = 0; t < 32; ++t) {
        int o = tid + t * 256, g = o >> 7, j = o & 127;
        float s = bm1[j];
        for (int k = 0; k < Hh; ++k) s += z[(g << 7) + k] * Wm1[k * Hh + j];
        r1[t] = fmaxf(s, 0.f);
    }
    __syncthreads();
#pragma unroll
    for (int t = 0; t < 32; ++t) z[tid + t * 256] = r1[t];
    __syncthreads();
#pragma unroll
    for (int t = 0; t < 32; ++t) {
        int o = tid + t * 256, g = o >> 7, j = o & 127;
        float s = bm2[j];
        for (int k = 0; k < Hh; ++k) s += z[(g << 7) + k] * Wm2[k * Hh + j];
        r1[t] = fmaxf(s, 0.f);
    }
    __syncthreads();
#pragma unroll
    for (int t = 0; t < 32; ++t) z[tid + t * 256] = r1[t];
    __syncthreads();
    if (tid < Gg * Cc) {
        int g = tid >> 1, c = tid & 1;
        float s = bm3[c];
        for (int k = 0; k < Hh; ++k) s += z[(g << 7) + k] * Wm3[k * Cc + c];
        out[tid] = s;
    }
}

// ---------------- launch -------------------------------------------------------
static void* symv(const void* s) {
    void* p = nullptr;
    cudaGetSymbolAddress(&p, s);
    return p;
}

extern "C" void kernel_launch(void* const* d_in, const int* in_sizes, int n_in,
                              void* d_out, int out_size) {
    const float* x    = (const float*)d_in[0];
    const int*   src  = (const int*)  d_in[1];
    const int*   dst  = (const int*)  d_in[2];
    const int*   gid  = (const int*)  d_in[3];
    const float* W_in = (const float*)d_in[4];
    const float* b_in = (const float*)d_in[5];
    const float* W1   = (const float*)d_in[6];
    const float* b1   = (const float*)d_in[7];
    const float* W2   = (const float*)d_in[8];
    const float* b2   = (const float*)d_in[9];
    const float* Wm1  = (const float*)d_in[10];
    const float* bm1  = (const float*)d_in[11];
    const float* Wm2  = (const float*)d_in[12];
    const float* bm2  = (const float*)d_in[13];
    const float* Wm3  = (const float*)d_in[14];
    const float* bm3  = (const float*)d_in[15];
    float* out = (float*)d_out;

    float*    p_h    = (float*)   symv(g_h);
    float*    p_out2 = (float*)   symv(g_out2);
    int*      p_cout = (int*)     symv(g_cout);
    int*      p_cin  = (int*)     symv(g_cin);
    float*    p_pool = (float*)   symv(g_pool);
    float*    p_cnt  = (float*)   symv(g_cnt);
    uint32_t* p_wst  = (uint32_t*)symv(g_wst);
    uint32_t* p_wtin = (uint32_t*)symv(g_wtin);
    float*    p_bsum = (float*)   symv(g_bsum);
    uint32_t* p_Ah   = (uint32_t*)symv(g_Ah);
    uint32_t* p_Al   = (uint32_t*)symv(g_Al);

    const int TB = 256;
    const int gemm_blocks = (Nn + 127) / 128;       // 782
    const int scan_blocks = (RN + 1023) / 1024;     // 391
    const int gat_blocks = (Nn * 32 + TB - 1) / TB;
    const int smem_gemm = 3 * STAGE_U * 4;          // 221184 bytes

    cudaFuncSetAttribute(bf16_gemm_kernel,
                         cudaFuncAttributeMaxDynamicSharedMemorySize, smem_gemm);

    // side stream + fork/join events (fresh per call; correctness + capture only)
    cudaStream_t s2;
    cudaEvent_t evF, evJ;
    cudaStreamCreateWithFlags(&s2, cudaStreamNonBlocking);
    cudaEventCreateWithFlags(&evF, cudaEventDisableTiming);
    cudaEventCreateWithFlags(&evJ, cudaEventDisableTiming);

    // ---- fork: side stream builds CSR + degrees + zero pool
    cudaEventRecord(evF, 0);
    cudaStreamWaitEvent(s2, evF, 0);

    cudaMemsetAsync(p_cout, 0, (size_t)RN * sizeof(int), s2);
    cudaMemsetAsync(p_cin,  0, (size_t)RN * sizeof(int), s2);
    degree_kernel<<<(RE + TB - 1) / TB, TB, 0, s2>>>(src, dst);
    scan1_kernel<<<scan_blocks, 256, 0, s2>>>();
    scan2_kernel<<<1, 512, 0, s2>>>(scan_blocks);
    scan3_kernel<<<scan_blocks, 256, 0, s2>>>();
    cudaMemsetAsync(p_cin, 0, (size_t)RN * sizeof(int), s2);
    fill_kernel<<<(RE + TB - 1) / TB, TB, 0, s2>>>(src, dst);
    cudaMemsetAsync(p_pool, 0, (size_t)Gg * Hh * sizeof(float), s2);
    cudaMemsetAsync(p_cnt,  0, (size_t)Gg * sizeof(float), s2);
    cudaEventRecord(evJ, s2);

    // ---- main stream: weights + input layer (independent of CSR)
    wprep_kernel<<<(2 * Hh * KU_L + Hh * KU_I + TB - 1) / TB, TB>>>(W1, W2, W_in);
    bsum_kernel<<<1, 128>>>(b1, b2);
    conv_kernel<<<(Nn * KU_I + TB - 1) / TB, TB>>>(x, KU_I, p_Ah, p_Al, Nn * KU_I);
    bf16_gemm_kernel<<<gemm_blocks, 512, smem_gemm>>>(
        p_Ah, p_Al, KU_I, p_wtin, b_in, 1, p_h, Nn);

    // ---- join: gathers need both CSR (side) and h0 (main)
    cudaStreamWaitEvent(0, evJ, 0);

    // --- layer 1: gather (warp per node,relation) -> stacked GEMM
    gather_kernel<<<dim3(gat_blocks, Rr), TB>>>(p_h, p_Ah, p_Al);
    bf16_gemm_kernel<<<gemm_blocks, 512, smem_gemm>>>(
        p_Ah, p_Al, KU_L, p_wst, p_bsum, 1, p_h, Nn);

    // --- layer 2
    gather_kernel<<<dim3(gat_blocks, Rr), TB>>>(p_h, p_Ah, p_Al);
    bf16_gemm_kernel<<<gemm_blocks, 512, smem_gemm>>>(
        p_Ah, p_Al, KU_L, p_wst + (size_t)WST, nullptr, 0, p_out2, Nn);

    // --- pool + head
    pool_kernel<<<((Nn + 15) / 16 * 32 + TB - 1) / TB, TB>>>(p_out2, gid);
    mlp_kernel<<<1, TB>>>(Wm1, bm1, Wm2, bm2, Wm3, bm3, out);
}

// round 17
// speedup vs baseline: 1.2719x; 1.1930x over previous
#include <cuda_runtime.h>
#include <cuda_bf16.h>
#include <math.h>
#include <stdint.h>

// Problem constants (fixed by the reference)
#define Nn 100000
#define Ee 400000
#define Rr 4
#define Gg 64
#define INF 64
#define Hh 128
#define Cc 2
#define RN (Rr * Nn)        // 400000
#define RE (Rr * Ee)        // 1600000

#define KU_L 256            // stacked K for layer GEMMs (512 k / 2)
#define KU_I 32             // input GEMM (64 k / 2)
#define WST  (2 * Hh * KU_L)
#define WST_IN (2 * Hh * KU_I)

// ---------------- scratch (device globals; no allocation allowed) ----------
__device__ float    g_h   [(size_t)Nn * Hh];
__device__ float    g_out2[(size_t)Nn * Hh];
__device__ float    g_rso [RN];
__device__ float    g_rsi [RN];
__device__ int      g_cout[RN];
__device__ int      g_cin [RN];
__device__ int      g_rp  [RN + 1];
__device__ int      g_bs  [512];
__device__ int      g_eidx  [RE];
__device__ float    g_escale[RE];
__device__ uint32_t g_wst   [2 * WST];
__device__ uint32_t g_wtin  [WST_IN];
__device__ float    g_bsum  [2 * Hh];
__device__ uint32_t g_Ah[(size_t)Nn * KU_L];
__device__ uint32_t g_Al[(size_t)Nn * KU_L];
__device__ float    g_pool[Gg * Hh];
__device__ float    g_cnt [Gg];

// ---------------- helpers ----------------------------------------------------
__device__ __forceinline__ uint32_t packbf_hi(float a, float b, float& ra, float& rb) {
    __nv_bfloat162 h = __floats2bfloat162_rn(a, b);
    ra = a - __bfloat162float(h.x);
    rb = b - __bfloat162float(h.y);
    return *reinterpret_cast<uint32_t*>(&h);
}
__device__ __forceinline__ uint32_t packbf(float a, float b) {
    __nv_bfloat162 h = __floats2bfloat162_rn(a, b);
    return *reinterpret_cast<uint32_t*>(&h);
}

__global__ void zero2_kernel(float4* a, int na4, float4* b, int nb4) {
    int i = blockIdx.x * blockDim.x + threadIdx.x;
    if (i < na4) a[i] = make_float4(0.f, 0.f, 0.f, 0.f);
    else if (i - na4 < nb4) b[i - na4] = make_float4(0.f, 0.f, 0.f, 0.f);
}

// ---------------- degrees ----------------------------------------------------
__global__ void degree_kernel(const int* __restrict__ src, const int* __restrict__ dst) {
    int i = blockIdx.x * blockDim.x + threadIdx.x;
    if (i < RE) {
        int r = i / Ee;
        atomicAdd(&g_cout[r * Nn + src[i]], 1);
        atomicAdd(&g_cin [r * Nn + dst[i]], 1);
    }
}
__global__ void rsq_kernel() {
    int i = blockIdx.x * blockDim.x + threadIdx.x;
    if (i < RN) {
        g_rso[i] = rsqrtf((float)max(g_cout[i], 1));
        g_rsi[i] = rsqrtf((float)max(g_cin [i], 1));
    }
}

// ---------------- CSR build: scan + fill --------------------------------------
__global__ void scan1_kernel() {
    __shared__ int ts[256];
    int b = blockIdx.x, t = threadIdx.x;
    int i0 = b * 1024 + t * 4;
    int v0 = (i0 + 0 < RN) ? g_cin[i0 + 0] : 0;
    int v1 = (i0 + 1 < RN) ? g_cin[i0 + 1] : 0;
    int v2 = (i0 + 2 < RN) ? g_cin[i0 + 2] : 0;
    int v3 = (i0 + 3 < RN) ? g_cin[i0 + 3] : 0;
    int tot = v0 + v1 + v2 + v3;
    ts[t] = tot;
    __syncthreads();
    for (int off = 1; off < 256; off <<= 1) {
        int x = (t >= off) ? ts[t - off] : 0;
        __syncthreads();
        ts[t] += x;
        __syncthreads();
    }
    int excl = ts[t] - tot;
    if (i0 + 0 < RN) g_rp[i0 + 0] = excl;
    if (i0 + 1 < RN) g_rp[i0 + 1] = excl + v0;
    if (i0 + 2 < RN) g_rp[i0 + 2] = excl + v0 + v1;
    if (i0 + 3 < RN) g_rp[i0 + 3] = excl + v0 + v1 + v2;
    if (t == 255) g_bs[b] = ts[255];
}
__global__ void scan2_kernel(int nb) {
    __shared__ int ts[512];
    int t = threadIdx.x;
    int v = (t < nb) ? g_bs[t] : 0;
    ts[t] = v;
    __syncthreads();
    for (int off = 1; off < 512; off <<= 1) {
        int x = (t >= off) ? ts[t - off] : 0;
        __syncthreads();
        ts[t] += x;
        __syncthreads();
    }
    g_bs[t] = ts[t] - v;
}
__global__ void scan3_kernel() {
    int b = blockIdx.x, t = threadIdx.x;
    int add = g_bs[b];
    int i0 = b * 1024 + t * 4;
#pragma unroll
    for (int q = 0; q < 4; ++q)
        if (i0 + q < RN) g_rp[i0 + q] += add;
    if (b == 0 && t == 0) g_rp[RN] = RE;
}
__global__ void fill_kernel(const int* __restrict__ src, const int* __restrict__ dst) {
    int i = blockIdx.x * blockDim.x + threadIdx.x;
    if (i >= RE) return;
    int r = i / Ee;
    int s = src[i];
    int idx = r * Nn + dst[i];
    int pos = g_rp[idx] + atomicAdd(&g_cin[idx], 1);
    g_eidx[pos] = s;
    g_escale[pos] = g_rso[r * Nn + s];
}

// ---------------- weight prep ---------------------------------------------------
__global__ void wprep_kernel(const float* __restrict__ W1,
                             const float* __restrict__ W2,
                             const float* __restrict__ Win) {
    int i = blockIdx.x * blockDim.x + threadIdx.x;
    const int TL = 2 * Hh * KU_L;
    if (i < TL) {
        int l = i >> 15;
        int rem = i & 32767;
        int n = rem >> 8, j = rem & 255;
        int r = j >> 6, ku = j & 63;
        const float* W = (l == 0 ? W1 : W2) + (size_t)r * Hh * Hh;
        float w0 = W[(2 * ku) * Hh + n];
        float w1 = W[(2 * ku + 1) * Hh + n];
        float r0, r1;
        uint32_t hi = packbf_hi(w0, w1, r0, r1);
        size_t base = (size_t)l * WST;
        g_wst[base + (size_t)n * KU_L + j] = hi;
        g_wst[base + (size_t)Hh * KU_L + (size_t)n * KU_L + j] = packbf(r0, r1);
    } else {
        int j = i - TL;
        if (j < Hh * KU_I) {
            int n = j >> 5, ku = j & 31;
            float w0 = Win[(2 * ku) * Hh + n];
            float w1 = Win[(2 * ku + 1) * Hh + n];
            float r0, r1;
            uint32_t hi = packbf_hi(w0, w1, r0, r1);
            g_wtin[n * KU_I + ku] = hi;
            g_wtin[Hh * KU_I + n * KU_I + ku] = packbf(r0, r1);
        }
    }
}

__global__ void bsum_kernel(const float* __restrict__ b1,
                            const float* __restrict__ b2) {
    int j = threadIdx.x;
    if (j < Hh) {
        float s1 = 0.f, s2 = 0.f;
        for (int r = 0; r < Rr; ++r) { s1 += b1[r * Hh + j]; s2 += b2[r * Hh + j]; }
        g_bsum[j] = s1; g_bsum[Hh + j] = s2;
    }
}

// ---------------- fp32 -> bf16 hi/lo planes for x -----------------------------
__global__ void conv_kernel(const float* __restrict__ src, int KU2,
                            uint32_t* __restrict__ ph, uint32_t* __restrict__ pl,
                            int total) {
    int i = blockIdx.x * blockDim.x + threadIdx.x;
    if (i >= total) return;
    int row = i / KU2, ku = i - row * KU2;
    float2 f = *(const float2*)(src + (size_t)row * (2 * KU2) + 2 * ku);
    float r0, r1;
    ph[i] = packbf_hi(f.x, f.y, r0, r1);
    pl[i] = packbf(r0, r1);
}

// ---------------- CSR gather: warp per (node, relation) ----------------------
__global__ void gather_kernel(const float* __restrict__ h,
                              uint32_t* __restrict__ Ah, uint32_t* __restrict__ Al) {
    int w = (blockIdx.x * blockDim.x + threadIdx.x) >> 5;
    int lane = threadIdx.x & 31;
    if (w >= Nn) return;
    int r = blockIdx.y;
    int idx = r * Nn + w;
    int p0 = __ldg(&g_rp[idx]);
    int p1 = __ldg(&g_rp[idx + 1]);
    float4 acc = make_float4(0.f, 0.f, 0.f, 0.f);
    int p = p0;
    for (; p + 4 <= p1; p += 4) {
        int s0 = __ldg(&g_eidx[p]);
        int s1 = __ldg(&g_eidx[p + 1]);
        int s2 = __ldg(&g_eidx[p + 2]);
        int s3 = __ldg(&g_eidx[p + 3]);
        float c0 = __ldg(&g_escale[p]);
        float c1 = __ldg(&g_escale[p + 1]);
        float c2 = __ldg(&g_escale[p + 2]);
        float c3 = __ldg(&g_escale[p + 3]);
        float4 v0 = *(const float4*)&h[(size_t)s0 * Hh + lane * 4];
        float4 v1 = *(const float4*)&h[(size_t)s1 * Hh + lane * 4];
        float4 v2 = *(const float4*)&h[(size_t)s2 * Hh + lane * 4];
        float4 v3 = *(const float4*)&h[(size_t)s3 * Hh + lane * 4];
        acc.x = fmaf(v0.x, c0, acc.x); acc.y = fmaf(v0.y, c0, acc.y);
        acc.z = fmaf(v0.z, c0, acc.z); acc.w = fmaf(v0.w, c0, acc.w);
        acc.x = fmaf(v1.x, c1, acc.x); acc.y = fmaf(v1.y, c1, acc.y);
        acc.z = fmaf(v1.z, c1, acc.z); acc.w = fmaf(v1.w, c1, acc.w);
        acc.x = fmaf(v2.x, c2, acc.x); acc.y = fmaf(v2.y, c2, acc.y);
        acc.z = fmaf(v2.z, c2, acc.z); acc.w = fmaf(v2.w, c2, acc.w);
        acc.x = fmaf(v3.x, c3, acc.x); acc.y = fmaf(v3.y, c3, acc.y);
        acc.z = fmaf(v3.z, c3, acc.z); acc.w = fmaf(v3.w, c3, acc.w);
    }
    for (; p < p1; ++p) {
        int s = __ldg(&g_eidx[p]);
        float sc = __ldg(&g_escale[p]);
        float4 v = *(const float4*)&h[(size_t)s * Hh + lane * 4];
        acc.x = fmaf(v.x, sc, acc.x);
        acc.y = fmaf(v.y, sc, acc.y);
        acc.z = fmaf(v.z, sc, acc.z);
        acc.w = fmaf(v.w, sc, acc.w);
    }
    float ri = __ldg(&g_rsi[idx]);
    acc.x *= ri; acc.y *= ri; acc.z *= ri; acc.w *= ri;
    float r0, r1, r2, r3;
    uint32_t h0 = packbf_hi(acc.x, acc.y, r0, r1);
    uint32_t h1 = packbf_hi(acc.z, acc.w, r2, r3);
    size_t base = (size_t)w * KU_L + r * 64 + 2 * lane;
    *(uint2*)&Ah[base] = make_uint2(h0, h1);
    *(uint2*)&Al[base] = make_uint2(packbf(r0, r1), packbf(r2, r3));
}

// ---------------- bf16 3-pass GEMM: 512 threads, 3-stage cp.async ------------
#define SMS 36
#define TILE_U (128 * SMS)
#define STAGE_U (4 * TILE_U)

__device__ __forceinline__ void mma16(float* c, const uint32_t* a,
                                      uint32_t b0, uint32_t b1) {
    asm volatile(
        "mma.sync.aligned.m16n8k16.row.col.f32.bf16.bf16.f32 "
        "{%0,%1,%2,%3}, {%4,%5,%6,%7}, {%8,%9}, {%0,%1,%2,%3};"
        : "+f"(c[0]), "+f"(c[1]), "+f"(c[2]), "+f"(c[3])
        : "r"(a[0]), "r"(a[1]), "r"(a[2]), "r"(a[3]), "r"(b0), "r"(b1));
}
__device__ __forceinline__ void cpa16(uint32_t daddr, const uint32_t* src, uint32_t nbytes) {
    asm volatile("cp.async.cg.shared.global [%0], [%1], 16, %2;"
                 :: "r"(daddr), "l"(src), "r"(nbytes) : "memory");
}

__global__ void __launch_bounds__(512)
bf16_gemm_kernel(const uint32_t* __restrict__ Ah, const uint32_t* __restrict__ Al,
                 int KU,
                 const uint32_t* __restrict__ Wp,
                 const float* __restrict__ cbias,   // nullable
                 int relu_out,
                 float* __restrict__ C, int n) {
    extern __shared__ uint32_t smu[];

    const int tid = threadIdx.x;
    const int lane = tid & 31, warp = tid >> 5;   // 16 warps
    const int wm = warp >> 1, wn = warp & 1;
    const int g = lane >> 2, t = lane & 3;
    const int row0 = blockIdx.x * 128;
    const int iters = KU >> 5;

    const int sr = tid >> 2;
    const int sc = (tid & 3) * 8;
    const int grow_s = row0 + sr;
    const int arow = (grow_s < n) ? grow_s : (n - 1);
    const uint32_t avalid = (grow_s < n) ? 16u : 0u;

    uint32_t smbase = (uint32_t)__cvta_generic_to_shared(smu);

    float acc[8][4];
#pragma unroll
    for (int nf = 0; nf < 8; ++nf)
#pragma unroll
        for (int q = 0; q < 4; ++q) acc[nf][q] = 0.f;

#define ISSUE(CI) do {                                                         \
    const int uc_ = (CI) * 32 + sc;                                            \
    const uint32_t dbase_ = smbase + ((CI) % 3) * (STAGE_U * 4);               \
    const uint32_t doff_ = (sr * SMS + sc) * 4;                                \
    const uint32_t* pAh_ = Ah + (size_t)arow * KU + uc_;                       \
    const uint32_t* pAl_ = Al + (size_t)arow * KU + uc_;                       \
    const uint32_t* pWh_ = Wp + (size_t)sr * KU + uc_;                         \
    const uint32_t* pWl_ = pWh_ + (size_t)Hh * KU;                             \
    _Pragma("unroll")                                                          \
    for (int q = 0; q < 2; ++q) {                                              \
        cpa16(dbase_ + doff_ + q * 16,                  pAh_ + q * 4, avalid); \
        cpa16(dbase_ + TILE_U * 4 + doff_ + q * 16,     pAl_ + q * 4, avalid); \
        cpa16(dbase_ + 2 * TILE_U * 4 + doff_ + q * 16, pWh_ + q * 4, 16u);    \
        cpa16(dbase_ + 3 * TILE_U * 4 + doff_ + q * 16, pWl_ + q * 4, 16u);    \
    }                                                                          \
    asm volatile("cp.async.commit_group;" ::: "memory");                       \
} while (0)

    ISSUE(0);
    if (iters > 1) ISSUE(1);

    for (int ci = 0; ci < iters; ++ci) {
        if (ci + 1 < iters)
            asm volatile("cp.async.wait_group 1;" ::: "memory");
        else
            asm volatile("cp.async.wait_group 0;" ::: "memory");
        __syncthreads();
        if (ci + 2 < iters) ISSUE(ci + 2);

        const uint32_t* base = smu + (ci % 3) * STAGE_U;
#pragma unroll
        for (int ks = 0; ks < 12; ++ks) {
            const int p = ks >> 2;
            const int kk = (ks & 3) * 8;
            const uint32_t* at = base + ((p == 1) ? TILE_U : 0);
            const uint32_t* bt = base + 2 * TILE_U + ((p == 2) ? TILE_U : 0);
            const int r_ = wm * 16 + g;
            uint32_t a[4];
            a[0] = at[(r_    ) * SMS + kk + t    ];
            a[1] = at[(r_ + 8) * SMS + kk + t    ];
            a[2] = at[(r_    ) * SMS + kk + t + 4];
            a[3] = at[(r_ + 8) * SMS + kk + t + 4];
#pragma unroll
            for (int nf = 0; nf < 8; ++nf) {
                int nr = wn * 64 + nf * 8 + g;
                uint32_t b0 = bt[nr * SMS + kk + t];
                uint32_t b1 = bt[nr * SMS + kk + t + 4];
                mma16(acc[nf], a, b0, b1);
            }
        }
    }
#undef ISSUE

    // ---- epilogue
#pragma unroll
    for (int half = 0; half < 2; ++half) {
        int grow = row0 + wm * 16 + g + half * 8;
        if (grow >= n) continue;
        float* crow = C + (size_t)grow * 128;
#pragma unroll
        for (int nf = 0; nf < 8; ++nf) {
            int col = wn * 64 + nf * 8 + 2 * t;
            float v0 = acc[nf][half * 2 + 0];
            float v1 = acc[nf][half * 2 + 1];
            if (cbias) { v0 += cbias[col]; v1 += cbias[col + 1]; }
            if (relu_out) { v0 = fmaxf(v0, 0.f); v1 = fmaxf(v1, 0.f); }
            float2 v; v.x = v0; v.y = v1;
            *(float2*)(crow + col) = v;
        }
    }
}

// ---------------- pooling (sorted-run accumulation, count fused) --------------
__device__ __forceinline__ void red_add_v4(float* p, float4 v) {
    asm volatile(
        "{\n\t.reg .u64 pg;\n\t"
        "cvta.to.global.u64 pg, %0;\n\t"
        "red.global.add.v4.f32 [pg], {%1,%2,%3,%4};\n\t}"
        :: "l"(p), "f"(v.x), "f"(v.y), "f"(v.z), "f"(v.w) : "memory");
}
__global__ void pool_kernel(const float* __restrict__ h, const int* __restrict__ gid) {
    int w = (blockIdx.x * blockDim.x + threadIdx.x) >> 5;
    int lane = threadIdx.x & 31;
    int n0 = w * 16;
    if (n0 >= Nn) return;
    int n1 = min(n0 + 16, Nn);
    int curg = __ldg(&gid[n0]);
    int runlen = 0;
    float4 acc = make_float4(0.f, 0.f, 0.f, 0.f);
    for (int node = n0; node < n1; ++node) {
        int g = __ldg(&gid[node]);
        if (g != curg) {
            red_add_v4(&g_pool[curg * Hh + lane * 4], acc);
            if (lane == 0) atomicAdd(&g_cnt[curg], (float)runlen);
            acc = make_float4(0.f, 0.f, 0.f, 0.f);
            runlen = 0;
            curg = g;
        }
        float4 v = *(const float4*)&h[(size_t)node * Hh + lane * 4];
        acc.x += v.x; acc.y += v.y; acc.z += v.z; acc.w += v.w;
        ++runlen;
    }
    red_add_v4(&g_pool[curg * Hh + lane * 4], acc);
    if (lane == 0) atomicAdd(&g_cnt[curg], (float)runlen);
}

// ---------------- MLP head: one block per graph -------------------------------
__global__ void mlp_kernel(const float* __restrict__ Wm1, const float* __restrict__ bm1,
                           const float* __restrict__ Wm2, const float* __restrict__ bm2,
                           const float* __restrict__ Wm3, const float* __restrict__ bm3,
                           float* __restrict__ out) {
    __shared__ float z[Hh], z2[Hh];
    int gidx = blockIdx.x;       // 0..Gg-1
    int j = threadIdx.x;         // 0..127
    z[j] = g_pool[gidx * Hh + j] / fmaxf(g_cnt[gidx], 1.f) + g_bsum[Hh + j];
    __syncthreads();
    // layer 1
    float s = bm1[j];
#pragma unroll 8
    for (int k = 0; k < Hh; ++k) s += z[k] * Wm1[k * Hh + j];
    z2[j] = fmaxf(s, 0.f);
    __syncthreads();
    // layer 2
    s = bm2[j];
#pragma unroll 8
    for (int k = 0; k < Hh; ++k) s += z2[k] * Wm2[k * Hh + j];
    z[j] = fmaxf(s, 0.f);
    __syncthreads();
    // layer 3
    if (j < Cc) {
        float s3 = bm3[j];
        for (int k = 0; k < Hh; ++k) s3 += z[k] * Wm3[k * Cc + j];
        out[gidx * Cc + j] = s3;
    }
}

// ---------------- launch -------------------------------------------------------
static void* symv(const void* s) {
    void* p = nullptr;
    cudaGetSymbolAddress(&p, s);
    return p;
}

extern "C" void kernel_launch(void* const* d_in, const int* in_sizes, int n_in,
                              void* d_out, int out_size) {
    const float* x    = (const float*)d_in[0];
    const int*   src  = (const int*)  d_in[1];
    const int*   dst  = (const int*)  d_in[2];
    const int*   gid  = (const int*)  d_in[3];
    const float* W_in = (const float*)d_in[4];
    const float* b_in = (const float*)d_in[5];
    const float* W1   = (const float*)d_in[6];
    const float* b1   = (const float*)d_in[7];
    const float* W2   = (const float*)d_in[8];
    const float* b2   = (const float*)d_in[9];
    const float* Wm1  = (const float*)d_in[10];
    const float* bm1  = (const float*)d_in[11];
    const float* Wm2  = (const float*)d_in[12];
    const float* bm2  = (const float*)d_in[13];
    const float* Wm3  = (const float*)d_in[14];
    const float* bm3  = (const float*)d_in[15];
    float* out = (float*)d_out;

    float*    p_h    = (float*)   symv(g_h);
    float*    p_out2 = (float*)   symv(g_out2);
    int*      p_cout = (int*)     symv(g_cout);
    int*      p_cin  = (int*)     symv(g_cin);
    float*    p_rso  = (float*)   symv(g_rso);
    float*    p_rsi  = (float*)   symv(g_rsi);
    float*    p_pool = (float*)   symv(g_pool);
    float*    p_cnt  = (float*)   symv(g_cnt);
    uint32_t* p_wst  = (uint32_t*)symv(g_wst);
    uint32_t* p_wtin = (uint32_t*)symv(g_wtin);
    float*    p_bsum = (float*)   symv(g_bsum);
    uint32_t* p_Ah   = (uint32_t*)symv(g_Ah);
    uint32_t* p_Al   = (uint32_t*)symv(g_Al);

    const int TB = 256;
    const int gemm_blocks = (Nn + 127) / 128;       // 782
    const int scan_blocks = (RN + 1023) / 1024;     // 391
    const int gat_blocks = (Nn * 32 + TB - 1) / TB;
    const int smem_gemm = 3 * STAGE_U * 4;          // 221184 bytes

    cudaFuncSetAttribute(bf16_gemm_kernel,
                         cudaFuncAttributeMaxDynamicSharedMemorySize, smem_gemm);

    // side stream + fork/join events (fresh per call; correctness + capture only)
    cudaStream_t s2;
    cudaEvent_t evF, evJ;
    cudaStreamCreateWithFlags(&s2, cudaStreamNonBlocking);
    cudaEventCreateWithFlags(&evF, cudaEventDisableTiming);
    cudaEventCreateWithFlags(&evJ, cudaEventDisableTiming);

    // ---- fork: side stream builds CSR + degrees + zero pool
    cudaEventRecord(evF, 0);
    cudaStreamWaitEvent(s2, evF, 0);

    zero2_kernel<<<(RN / 2 + TB - 1) / TB, TB, 0, s2>>>(
        (float4*)p_cout, RN / 4, (float4*)p_cin, RN / 4);
    degree_kernel<<<(RE + TB - 1) / TB, TB, 0, s2>>>(src, dst);
    rsq_kernel<<<(RN + TB - 1) / TB, TB, 0, s2>>>();
    scan1_kernel<<<scan_blocks, 256, 0, s2>>>();
    scan2_kernel<<<1, 512, 0, s2>>>(scan_blocks);
    scan3_kernel<<<scan_blocks, 256, 0, s2>>>();
    zero2_kernel<<<(RN / 4 + TB - 1) / TB, TB, 0, s2>>>(
        (float4*)p_cin, RN / 4, (float4*)p_cin, 0);
    fill_kernel<<<(RE + TB - 1) / TB, TB, 0, s2>>>(src, dst);
    zero2_kernel<<<(Gg * Hh / 4 + Gg / 4 + TB - 1) / TB, TB, 0, s2>>>(
        (float4*)p_pool, Gg * Hh / 4, (float4*)p_cnt, Gg / 4);
    cudaEventRecord(evJ, s2);

    // ---- main stream: weights + input layer (independent of CSR)
    wprep_kernel<<<(2 * Hh * KU_L + Hh * KU_I + TB - 1) / TB, TB>>>(W1, W2, W_in);
    bsum_kernel<<<1, 128>>>(b1, b2);
    conv_kernel<<<(Nn * KU_I + TB - 1) / TB, TB>>>(x, KU_I, p_Ah, p_Al, Nn * KU_I);
    bf16_gemm_kernel<<<gemm_blocks, 512, smem_gemm>>>(
        p_Ah, p_Al, KU_I, p_wtin, b_in, 1, p_h, Nn);

    // ---- join: gathers need both CSR (side) and h0 (main)
    cudaStreamWaitEvent(0, evJ, 0);

    // --- layer 1: gather (warp per node,relation) -> stacked GEMM
    gather_kernel<<<dim3(gat_blocks, Rr), TB>>>(p_h, p_Ah, p_Al);
    bf16_gemm_kernel<<<gemm_blocks, 512, smem_gemm>>>(
        p_Ah, p_Al, KU_L, p_wst, p_bsum, 1, p_h, Nn);

    // --- layer 2
    gather_kernel<<<dim3(gat_blocks, Rr), TB>>>(p_h, p_Ah, p_Al);
    bf16_gemm_kernel<<<gemm_blocks, 512, smem_gemm>>>(
        p_Ah, p_Al, KU_L, p_wst + (size_t)WST, nullptr, 0, p_out2, Nn);

    // --- pool + head (MLP parallel: one block per graph)
    pool_kernel<<<((Nn + 15) / 16 * 32 + TB - 1) / TB, TB>>>(p_out2, gid);
    mlp_kernel<<<Gg, 128>>>(Wm1, bm1, Wm2, bm2, Wm3, bm3, out);
}